// round 5
// baseline (speedup 1.0000x reference)
#include <cuda_runtime.h>
#include <math.h>

#define NN 50000
#define NE 800000
#define FIN 64
#define HD 96
#define H4 24        // HD / 4
#define NG 256
#define GROWS 24
#define SCB 512
#define NSCB ((NN + SCB - 1) / SCB)   // 98

// ---------------- scratch (device globals; no runtime allocation) -----------
__device__ __align__(16) float g_h0[NN * HD];     // layer output ping
__device__ __align__(16) float g_h1[NN * HD];     // layer output pong
__device__ float g_dinv[NN];
__device__ int   g_deg[NN];
__device__ int   g_coff[NN + 1];                  // CSR offsets (by dst)
__device__ int   g_cur[NN];                       // fill cursors
__device__ __align__(8) int2 g_edge[NE];          // packed (src, norm-bits)
__device__ int   g_bsum[NSCB];
__device__ float g_gate[NN];
__device__ float g_gden[NG];
__device__ __align__(16) float g_att[2][NG * FIN];
__device__ __align__(16) float g_pool[2][NG * HD];
__device__ int   g_cnt[2][NG];

// ---------------- helpers ----------------------------------------------------
__device__ __forceinline__ void red4(float* p, float4 v) {
    asm volatile("red.global.add.v4.f32 [%0], {%1,%2,%3,%4};"
                 :: "l"(p), "f"(v.x), "f"(v.y), "f"(v.z), "f"(v.w) : "memory");
}

// ---------------- init per side ----------------------------------------------
__global__ void k_init(int side) {
    int i = blockIdx.x * blockDim.x + threadIdx.x;
    if (i < NN) g_deg[i] = 0;
    if (i < NG) { g_gden[i] = 0.f; g_cnt[side][i] = 0; }
    if (i < NG * FIN) g_att[side][i] = 0.f;
    if (i < NG * HD)  g_pool[side][i] = 0.f;
}

__global__ void k_deg(const int* __restrict__ ei) {
    int e = blockIdx.x * blockDim.x + threadIdx.x;
    if (e < NE) atomicAdd(&g_deg[ei[NE + e]], 1);
}

// ---------------- CSR build: scan of degrees, then fill ----------------------
__global__ void k_scan1() {
    __shared__ int s[SCB];
    int i = blockIdx.x * SCB + threadIdx.x;
    s[threadIdx.x] = (i < NN) ? g_deg[i] : 0;
    __syncthreads();
    for (int o = SCB / 2; o > 0; o >>= 1) {
        if (threadIdx.x < o) s[threadIdx.x] += s[threadIdx.x + o];
        __syncthreads();
    }
    if (threadIdx.x == 0) g_bsum[blockIdx.x] = s[0];
}

__global__ void k_scan2() {
    if (threadIdx.x == 0) {
        int acc = 0;
        for (int b = 0; b < NSCB; b++) { int t = g_bsum[b]; g_bsum[b] = acc; acc += t; }
        g_coff[NN] = acc;
    }
}

__global__ void k_scan3() {
    __shared__ int s[SCB];
    int i = blockIdx.x * SCB + threadIdx.x;
    int t = threadIdx.x;
    int v = (i < NN) ? g_deg[i] : 0;
    s[t] = v;
    __syncthreads();
    for (int o = 1; o < SCB; o <<= 1) {
        int a = (t >= o) ? s[t - o] : 0;
        __syncthreads();
        s[t] += a;
        __syncthreads();
    }
    if (i < NN) {
        int off = g_bsum[blockIdx.x] + s[t] - v;   // exclusive
        g_coff[i] = off;
        g_cur[i] = off;
        g_dinv[i] = rsqrtf((float)v + 1.0f);
    }
}

__global__ void k_csrfill(const int* __restrict__ ei) {
    int e = blockIdx.x * blockDim.x + threadIdx.x;
    if (e < NE) {
        int s = ei[e], d = ei[NE + e];
        float norm = g_dinv[s] * g_dinv[d];
        int slot = atomicAdd(&g_cur[d], 1);
        g_edge[slot] = make_int2(s, __float_as_int(norm));
    }
}

// ---------------- attention gate ----------------------------------------------
__global__ void k_gate(const float* __restrict__ x, const int* __restrict__ batch,
                       const float* __restrict__ gW1, const float* __restrict__ gb1,
                       const float* __restrict__ gW2, const float* __restrict__ gb2,
                       int side) {
    int lane = threadIdx.x & 31;
    int n = blockIdx.x * (blockDim.x >> 5) + (threadIdx.x >> 5);
    if (n >= NN) return;
    float xa = x[n * FIN + lane];
    float xb = x[n * FIN + 32 + lane];
    float acc0 = gb1[lane];
    float acc1 = gb1[lane + 32];
#pragma unroll
    for (int k = 0; k < FIN; k++) {
        float xk = __shfl_sync(0xffffffffu, (k < 32) ? xa : xb, k & 31);
        acc0 += xk * gW1[k * FIN + lane];
        acc1 += xk * gW1[k * FIN + lane + 32];
    }
    float h = fmaxf(acc0, 0.f) * gW2[lane] + fmaxf(acc1, 0.f) * gW2[lane + 32];
#pragma unroll
    for (int o = 16; o > 0; o >>= 1) h += __shfl_down_sync(0xffffffffu, h, o);
    if (lane == 0) {
        // gates are tiny (|g| << 80): exp without max-shift is exact for the softmax ratio
        float e = expf(h + gb2[0]);
        g_gate[n] = e;
        atomicAdd(&g_gden[batch[n]], e);
        atomicAdd(&g_cnt[side][batch[n]], 1);
    }
}

__global__ void k_attpool(const float* __restrict__ x, const int* __restrict__ batch, int side) {
    int idx = blockIdx.x * blockDim.x + threadIdx.x;     // NN * 16 chunks
    if (idx >= NN * (FIN / 4)) return;
    int n = idx >> 4, j = idx & 15;
    int b = batch[n];
    float alpha = g_gate[n] / g_gden[b];
    float4 v = ((const float4*)x)[n * (FIN / 4) + j];
    v.x *= alpha; v.y *= alpha; v.z *= alpha; v.w *= alpha;
    red4(&g_att[side][b * FIN + j * 4], v);
}

// ---------------- fused gather + GEMM -----------------------------------------
// inSel: 0 = external feat, 1 = g_h0, 2 = g_h1.  outSel: 0 = g_h0, 1 = g_h1.
// For each 24-row tile: gather agg rows into Xs (CSR pull), then GEMM @ W + bias.
// reluOut applies relu before store; fusePool reduces rows into g_pool instead.
__global__ void __launch_bounds__(144) k_fused(
        const float* __restrict__ featExt, int inSel, int K4,
        const float* __restrict__ W, const float* __restrict__ bias,
        int reluOut, int fusePool, int outSel, const int* __restrict__ batch, int side) {
    const int K = K4 * 4;
    const int KS = HD + 4;                          // fixed stride, 16B-aligned rows
    __shared__ __align__(16) float Ws[HD * HD];
    __shared__ __align__(16) float Xs[GROWS * (HD + 4)];
    const float4* f4 = (inSel == 0) ? (const float4*)featExt
                     : (inSel == 1) ? (const float4*)g_h0 : (const float4*)g_h1;
    float4* out4 = outSel ? (float4*)g_h1 : (float4*)g_h0;
    const int tx = threadIdx.x;                     // 0..23
    const int ty = threadIdx.y;                     // 0..5
    const int tid = ty * 24 + tx;

    for (int i = tid; i < K * HD; i += 144) Ws[i] = W[i];
    float4 bb = __ldg(&((const float4*)bias)[tx]);
    const int rb = ty * 4;

    for (int t0 = blockIdx.x * GROWS; t0 < NN; t0 += gridDim.x * GROWS) {
        __syncthreads();                            // Xs free from prior GEMM
        // ---- gather phase: thread (tx<K4) does chunk tx of rows rb..rb+3 ----
        if (tx < K4) {
#pragma unroll
            for (int r = 0; r < 4; r++) {
                int row = t0 + rb + r;
                float4 acc = {0.f, 0.f, 0.f, 0.f};
                if (row < NN) {
                    float dv = g_dinv[row];
                    float s = dv * dv;
                    float4 v = __ldg(&f4[row * K4 + tx]);
                    acc.x = s * v.x; acc.y = s * v.y; acc.z = s * v.z; acc.w = s * v.w;
                    int p = __ldg(&g_coff[row]);
                    int end = __ldg(&g_coff[row + 1]);
                    for (; p + 1 < end; p += 2) {
                        int2 e0 = __ldg(&g_edge[p]);
                        int2 e1 = __ldg(&g_edge[p + 1]);
                        float w0 = __int_as_float(e0.y);
                        float w1 = __int_as_float(e1.y);
                        float4 a = __ldg(&f4[e0.x * K4 + tx]);
                        float4 b = __ldg(&f4[e1.x * K4 + tx]);
                        acc.x += w0 * a.x + w1 * b.x;
                        acc.y += w0 * a.y + w1 * b.y;
                        acc.z += w0 * a.z + w1 * b.z;
                        acc.w += w0 * a.w + w1 * b.w;
                    }
                    if (p < end) {
                        int2 e0 = __ldg(&g_edge[p]);
                        float w0 = __int_as_float(e0.y);
                        float4 a = __ldg(&f4[e0.x * K4 + tx]);
                        acc.x += w0 * a.x; acc.y += w0 * a.y;
                        acc.z += w0 * a.z; acc.w += w0 * a.w;
                    }
                }
                *(float4*)&Xs[(rb + r) * KS + tx * 4] = acc;
            }
        }
        __syncthreads();
        // ---- GEMM phase: out[24,96] = Xs[24,K] @ Ws[K,96] + bias ----
        float4 a0 = bb, a1 = bb, a2 = bb, a3 = bb;
        const float4* Ws4 = (const float4*)Ws;
        for (int k = 0; k < K; k++) {
            float4 w = Ws4[k * H4 + tx];
            float x0 = Xs[(rb + 0) * KS + k];
            float x1 = Xs[(rb + 1) * KS + k];
            float x2 = Xs[(rb + 2) * KS + k];
            float x3 = Xs[(rb + 3) * KS + k];
            a0.x += x0 * w.x; a0.y += x0 * w.y; a0.z += x0 * w.z; a0.w += x0 * w.w;
            a1.x += x1 * w.x; a1.y += x1 * w.y; a1.z += x1 * w.z; a1.w += x1 * w.w;
            a2.x += x2 * w.x; a2.y += x2 * w.y; a2.z += x2 * w.z; a2.w += x2 * w.w;
            a3.x += x3 * w.x; a3.y += x3 * w.y; a3.z += x3 * w.z; a3.w += x3 * w.w;
        }
        if (reluOut) {
            a0.x = fmaxf(a0.x, 0.f); a0.y = fmaxf(a0.y, 0.f); a0.z = fmaxf(a0.z, 0.f); a0.w = fmaxf(a0.w, 0.f);
            a1.x = fmaxf(a1.x, 0.f); a1.y = fmaxf(a1.y, 0.f); a1.z = fmaxf(a1.z, 0.f); a1.w = fmaxf(a1.w, 0.f);
            a2.x = fmaxf(a2.x, 0.f); a2.y = fmaxf(a2.y, 0.f); a2.z = fmaxf(a2.z, 0.f); a2.w = fmaxf(a2.w, 0.f);
            a3.x = fmaxf(a3.x, 0.f); a3.y = fmaxf(a3.y, 0.f); a3.z = fmaxf(a3.z, 0.f); a3.w = fmaxf(a3.w, 0.f);
        }
        int r0 = t0 + rb;
        if (!fusePool) {
            if (r0 + 0 < NN) out4[(r0 + 0) * H4 + tx] = a0;
            if (r0 + 1 < NN) out4[(r0 + 1) * H4 + tx] = a1;
            if (r0 + 2 < NN) out4[(r0 + 2) * H4 + tx] = a2;
            if (r0 + 3 < NN) out4[(r0 + 3) * H4 + tx] = a3;
        } else {
            if (r0 + 0 < NN) red4(&g_pool[side][batch[r0 + 0] * HD + tx * 4], a0);
            if (r0 + 1 < NN) red4(&g_pool[side][batch[r0 + 1] * HD + tx * 4], a1);
            if (r0 + 2 < NN) red4(&g_pool[side][batch[r0 + 2] * HD + tx * 4], a2);
            if (r0 + 3 < NN) red4(&g_pool[side][batch[r0 + 3] * HD + tx * 4], a3);
        }
    }
}

// ---------------- final MLP ---------------------------------------------------
__global__ void k_final(const float* __restrict__ lW0, const float* __restrict__ lb0,
                        const float* __restrict__ lW1, const float* __restrict__ lb1,
                        float* __restrict__ out) {
    int g = blockIdx.x;
    int j = threadIdx.x;                                 // 96 threads
    __shared__ float cat[2 * HD + 2 * FIN];              // 320
    __shared__ float red[HD];
    for (int i = j; i < 2 * HD + 2 * FIN; i += HD) {
        float v;
        if (i < HD)            v = g_pool[0][g * HD + i] / fmaxf((float)g_cnt[0][g], 1.f);
        else if (i < 2 * HD)   v = g_pool[1][g * HD + (i - HD)] / fmaxf((float)g_cnt[1][g], 1.f);
        else if (i < 2 * HD + FIN) v = g_att[0][g * FIN + (i - 2 * HD)];
        else                   v = g_att[1][g * FIN + (i - 2 * HD - FIN)];
        cat[i] = v;
    }
    __syncthreads();
    float acc = lb0[j];
#pragma unroll 8
    for (int i = 0; i < 2 * HD + 2 * FIN; i++)
        acc += cat[i] * lW0[i * HD + j];
    red[j] = fmaxf(acc, 0.f) * lW1[j];
    __syncthreads();
    if (j == 0) {
        float s = lb1[0];
        for (int t = 0; t < HD; t++) s += red[t];
        out[g] = s;
    }
}

// ---------------- host launcher ----------------------------------------------
extern "C" void kernel_launch(void* const* d_in, const int* in_sizes, int n_in,
                              void* d_out, int out_size) {
    const float* gW1 = (const float*)d_in[20];
    const float* gb1 = (const float*)d_in[21];
    const float* gW2 = (const float*)d_in[22];
    const float* gb2 = (const float*)d_in[23];
    const float* lW0 = (const float*)d_in[24];
    const float* lb0 = (const float*)d_in[25];
    const float* lW1 = (const float*)d_in[26];
    const float* lb1 = (const float*)d_in[27];

    const int TB = 256;
    const int GB_N  = (NN + TB - 1) / TB;
    const int GB_E  = (NE + TB - 1) / TB;
    const int GB_G16 = (NN * 16 + TB - 1) / TB;
    const int FUSED_GRID = 592;
    dim3 fusedBlk(24, 6);

    for (int side = 0; side < 2; side++) {
        const float* x     = (const float*)d_in[side];        // x_p / x_d
        const int*   ei    = (const int*)d_in[4 + side];      // edge_index
        const int*   batch = (const int*)d_in[6 + side];      // batch
        const float* W0 = (const float*)d_in[8 + 6 * side];
        const float* b0 = (const float*)d_in[9 + 6 * side];
        const float* W1 = (const float*)d_in[10 + 6 * side];
        const float* b1 = (const float*)d_in[11 + 6 * side];
        const float* W2 = (const float*)d_in[12 + 6 * side];
        const float* b2 = (const float*)d_in[13 + 6 * side];

        k_init<<<GB_N, TB>>>(side);
        k_deg<<<GB_E, TB>>>(ei);

        // CSR build (by dst) + dinv
        k_scan1<<<NSCB, SCB>>>();
        k_scan2<<<1, 32>>>();
        k_scan3<<<NSCB, SCB>>>();
        k_csrfill<<<GB_E, TB>>>(ei);

        // attention pooling on raw features
        k_gate<<<(NN + 7) / 8, 256>>>(x, batch, gW1, gb1, gW2, gb2, side);
        k_attpool<<<GB_G16, TB>>>(x, batch, side);

        // layer 0: gather x (K=64) + GEMM 64->96, relu -> g_h0
        k_fused<<<FUSED_GRID, fusedBlk>>>(x, 0, 16, W0, b0, 1, 0, 0, batch, side);
        // layer 1: gather g_h0 (K=96) + GEMM 96->96, relu -> g_h1
        k_fused<<<FUSED_GRID, fusedBlk>>>(nullptr, 1, 24, W1, b1, 1, 0, 1, batch, side);
        // layer 2: gather g_h1 + GEMM 96->96 fused with mean-pool sum
        k_fused<<<FUSED_GRID, fusedBlk>>>(nullptr, 2, 24, W2, b2, 0, 1, 0, batch, side);
    }

    k_final<<<NG, HD>>>(lW0, lb0, lW1, lb1, (float*)d_out);
}

// round 6
// speedup vs baseline: 1.2995x; 1.2995x over previous
#include <cuda_runtime.h>
#include <math.h>

#define NN 50000
#define NN2 100000
#define NE 800000
#define NE2 1600000
#define FIN 64
#define HD 96
#define H4 24        // HD / 4
#define NG 256
#define GROWS 24
#define SCB 512
#define NSCB2 ((NN2 + SCB - 1) / SCB)   // 196

// ---------------- scratch (device globals; no runtime allocation) -----------
__device__ __align__(16) float g_h[NN2 * HD];     // layer outputs (both sides)
__device__ __align__(16) float g_agg[NN2 * HD];   // gather outputs (both sides)
__device__ float g_dinv[NN2];
__device__ int   g_deg[NN2];
__device__ int   g_coff[NN2 + 1];                 // CSR offsets (by global dst)
__device__ int   g_cur[NN2];
__device__ __align__(8) int2 g_edge[NE2];         // (local src, norm-bits)
__device__ int   g_bsum[256];
__device__ float g_gate[NN2];
__device__ float g_gden[2][NG];
__device__ __align__(16) float g_att[2][NG * FIN];
__device__ __align__(16) float g_pool[2][NG * HD];
__device__ int   g_cnt[2][NG];

// ---------------- helpers ----------------------------------------------------
__device__ __forceinline__ void red4(float* p, float4 v) {
    asm volatile("red.global.add.v4.f32 [%0], {%1,%2,%3,%4};"
                 :: "l"(p), "f"(v.x), "f"(v.y), "f"(v.z), "f"(v.w) : "memory");
}

union F2U { float2 f; unsigned long long u; };
__device__ __forceinline__ float2 ffma2(float2 a, float2 b, float2 c) {
    F2U ua, ub, uc, ud;
    ua.f = a; ub.f = b; uc.f = c;
    asm("fma.rn.f32x2 %0, %1, %2, %3;"
        : "=l"(ud.u) : "l"(ua.u), "l"(ub.u), "l"(uc.u));
    return ud.f;
}

// ---------------- init ---------------------------------------------------------
__global__ void k_init() {
    int i = blockIdx.x * blockDim.x + threadIdx.x;
    if (i < NN2) g_deg[i] = 0;
    if (i < NG) {
        g_gden[0][i] = 0.f; g_gden[1][i] = 0.f;
        g_cnt[0][i] = 0;    g_cnt[1][i] = 0;
    }
    if (i < NG * FIN) { g_att[0][i] = 0.f; g_att[1][i] = 0.f; }
    if (i < NG * HD)  { g_pool[0][i] = 0.f; g_pool[1][i] = 0.f; }
}

__global__ void k_deg(const int* __restrict__ eip, const int* __restrict__ eid) {
    int e = blockIdx.x * blockDim.x + threadIdx.x;
    if (e >= NE2) return;
    int side = (e >= NE);
    int el = e - side * NE;
    const int* ei = side ? eid : eip;
    atomicAdd(&g_deg[side * NN + ei[NE + el]], 1);
}

// ---------------- CSR build ----------------------------------------------------
__global__ void k_scan1() {
    __shared__ int s[SCB];
    int i = blockIdx.x * SCB + threadIdx.x;
    s[threadIdx.x] = (i < NN2) ? g_deg[i] : 0;
    __syncthreads();
    for (int o = SCB / 2; o > 0; o >>= 1) {
        if (threadIdx.x < o) s[threadIdx.x] += s[threadIdx.x + o];
        __syncthreads();
    }
    if (threadIdx.x == 0) g_bsum[blockIdx.x] = s[0];
}

__global__ void k_scan2() {
    __shared__ int s[256];
    int t = threadIdx.x;
    int v = (t < NSCB2) ? g_bsum[t] : 0;
    s[t] = v;
    __syncthreads();
    for (int o = 1; o < 256; o <<= 1) {
        int a = (t >= o) ? s[t - o] : 0;
        __syncthreads();
        s[t] += a;
        __syncthreads();
    }
    if (t < NSCB2) g_bsum[t] = s[t] - v;        // exclusive
    if (t == 255) g_coff[NN2] = s[255];
}

__global__ void k_scan3() {
    __shared__ int s[SCB];
    int i = blockIdx.x * SCB + threadIdx.x;
    int t = threadIdx.x;
    int v = (i < NN2) ? g_deg[i] : 0;
    s[t] = v;
    __syncthreads();
    for (int o = 1; o < SCB; o <<= 1) {
        int a = (t >= o) ? s[t - o] : 0;
        __syncthreads();
        s[t] += a;
        __syncthreads();
    }
    if (i < NN2) {
        int off = g_bsum[blockIdx.x] + s[t] - v;
        g_coff[i] = off;
        g_cur[i] = off;
        g_dinv[i] = rsqrtf((float)v + 1.0f);
    }
}

__global__ void k_csrfill(const int* __restrict__ eip, const int* __restrict__ eid) {
    int e = blockIdx.x * blockDim.x + threadIdx.x;
    if (e >= NE2) return;
    int side = (e >= NE);
    int el = e - side * NE;
    const int* ei = side ? eid : eip;
    int s = ei[el], d = ei[NE + el];
    int base = side * NN;
    float norm = g_dinv[base + s] * g_dinv[base + d];
    int slot = atomicAdd(&g_cur[base + d], 1);
    g_edge[slot] = make_int2(s, __float_as_int(norm));   // src stored LOCAL
}

// ---------------- attention gate (both sides) ----------------------------------
__global__ void k_gate(const float* __restrict__ xp, const float* __restrict__ xd,
                       const int* __restrict__ bp, const int* __restrict__ bd,
                       const float* __restrict__ gW1, const float* __restrict__ gb1,
                       const float* __restrict__ gW2, const float* __restrict__ gb2) {
    int lane = threadIdx.x & 31;
    int n = blockIdx.x * (blockDim.x >> 5) + (threadIdx.x >> 5);
    if (n >= NN2) return;
    int side = (n >= NN);
    int nl = n - side * NN;
    const float* x = side ? xd : xp;
    const int* batch = side ? bd : bp;
    float xa = x[nl * FIN + lane];
    float xb = x[nl * FIN + 32 + lane];
    float acc0 = gb1[lane];
    float acc1 = gb1[lane + 32];
#pragma unroll
    for (int k = 0; k < FIN; k++) {
        float xk = __shfl_sync(0xffffffffu, (k < 32) ? xa : xb, k & 31);
        acc0 += xk * gW1[k * FIN + lane];
        acc1 += xk * gW1[k * FIN + lane + 32];
    }
    float h = fmaxf(acc0, 0.f) * gW2[lane] + fmaxf(acc1, 0.f) * gW2[lane + 32];
#pragma unroll
    for (int o = 16; o > 0; o >>= 1) h += __shfl_down_sync(0xffffffffu, h, o);
    if (lane == 0) {
        // gates tiny: exp without max-shift is exact for the softmax ratio
        float e = expf(h + gb2[0]);
        g_gate[n] = e;
        int b = batch[nl];
        atomicAdd(&g_gden[side][b], e);
        atomicAdd(&g_cnt[side][b], 1);
    }
}

__global__ void k_attpool(const float* __restrict__ xp, const float* __restrict__ xd,
                          const int* __restrict__ bp, const int* __restrict__ bd) {
    int idx = blockIdx.x * blockDim.x + threadIdx.x;     // NN2 * 16
    if (idx >= NN2 * (FIN / 4)) return;
    int n = idx >> 4, j = idx & 15;
    int side = (n >= NN);
    int nl = n - side * NN;
    int b = side ? bd[nl] : bp[nl];
    float alpha = g_gate[n] / g_gden[side][b];
    const float4* x4 = side ? (const float4*)xd : (const float4*)xp;
    float4 v = __ldg(&x4[nl * (FIN / 4) + j]);
    v.x *= alpha; v.y *= alpha; v.z *= alpha; v.w *= alpha;
    red4(&g_att[side][b * FIN + j * 4], v);
}

// ---------------- CSR gather (both sides): g_agg[n] = self + sum norm*feat[src] --
__global__ void k_gather(const float4* __restrict__ fp, const float4* __restrict__ fd,
                         int useH, int K4) {
    int idx = blockIdx.x * blockDim.x + threadIdx.x;
    if (idx >= NN2 * K4) return;
    int n = idx / K4, j = idx - n * K4;
    int side = (n >= NN);
    int nl = n - side * NN;
    const float4* f4 = useH ? ((const float4*)g_h) + (size_t)side * NN * K4
                            : (side ? fd : fp);
    float dv = g_dinv[n];
    float4 v = __ldg(&f4[(size_t)nl * K4 + j]);
    float s = dv * dv;
    float4 acc = { s * v.x, s * v.y, s * v.z, s * v.w };
    int p = __ldg(&g_coff[n]);
    int end = __ldg(&g_coff[n + 1]);
    for (; p + 1 < end; p += 2) {
        int2 e0 = __ldg(&g_edge[p]);
        int2 e1 = __ldg(&g_edge[p + 1]);
        float w0 = __int_as_float(e0.y);
        float w1 = __int_as_float(e1.y);
        float4 a = __ldg(&f4[(size_t)e0.x * K4 + j]);
        float4 b = __ldg(&f4[(size_t)e1.x * K4 + j]);
        acc.x += w0 * a.x + w1 * b.x;
        acc.y += w0 * a.y + w1 * b.y;
        acc.z += w0 * a.z + w1 * b.z;
        acc.w += w0 * a.w + w1 * b.w;
    }
    if (p < end) {
        int2 e0 = __ldg(&g_edge[p]);
        float w0 = __int_as_float(e0.y);
        float4 a = __ldg(&f4[(size_t)e0.x * K4 + j]);
        acc.x += w0 * a.x; acc.y += w0 * a.y; acc.z += w0 * a.z; acc.w += w0 * a.w;
    }
    ((float4*)g_agg)[idx] = acc;
}

// ---------------- GEMM (both sides, f32x2 FMA): g_h = g_agg @ W + b ------------
// blockIdx.x & 1 selects side; Ws2 holds W interleaved as (k even, k odd) pairs.
__global__ void __launch_bounds__(144) k_gemm(
        const float* __restrict__ Wp, const float* __restrict__ Wd,
        const float* __restrict__ bp, const float* __restrict__ bd,
        int K4, int reluOut, int fusePool,
        const int* __restrict__ batch_p, const int* __restrict__ batch_d) {
    const int K = K4 * 4;
    const int KP = K4 * 2;          // k-pairs
    const int KS = K + 4;           // Xs row stride (floats), /4 == int
    __shared__ __align__(16) float Ws2[48 * 192];       // max K=96
    __shared__ __align__(16) float Xs[GROWS * 100];
    const int side = blockIdx.x & 1;
    const int blk = blockIdx.x >> 1;
    const int nblk = gridDim.x >> 1;
    const float* W = side ? Wd : Wp;
    const float* bias = side ? bd : bp;
    const int* batch = side ? batch_d : batch_p;
    const float4* X4 = ((const float4*)g_agg) + (size_t)side * NN * K4;
    const int tx = threadIdx.x, ty = threadIdx.y;
    const int tid = ty * 24 + tx;

    for (int i = tid; i < K * HD; i += 144) {
        int k = i / HD, c = i - k * HD;
        Ws2[(k >> 1) * 192 + c * 2 + (k & 1)] = W[i];
    }
    float4 bb = __ldg(&((const float4*)bias)[tx]);
    const int rb = ty * 4;
    const float4* W4 = (const float4*)Ws2;

    for (int t0 = blk * GROWS; t0 < NN; t0 += nblk * GROWS) {
        __syncthreads();
        for (int i = tid; i < GROWS * K4; i += 144) {
            int r = i / K4, c4 = i - r * K4;
            int row = t0 + r;
            float4 v = (row < NN) ? __ldg(&X4[(size_t)row * K4 + c4])
                                  : make_float4(0.f, 0.f, 0.f, 0.f);
            *(float4*)&Xs[r * KS + c4 * 4] = v;
        }
        __syncthreads();

        float2 acc[4][4];
#pragma unroll
        for (int r = 0; r < 4; r++)
#pragma unroll
            for (int c = 0; c < 4; c++) acc[r][c] = make_float2(0.f, 0.f);

        for (int kp = 0; kp < KP; kp++) {
            float4 wA = W4[kp * 48 + tx * 2];
            float4 wB = W4[kp * 48 + tx * 2 + 1];
            float2 wc0 = make_float2(wA.x, wA.y);
            float2 wc1 = make_float2(wA.z, wA.w);
            float2 wc2 = make_float2(wB.x, wB.y);
            float2 wc3 = make_float2(wB.z, wB.w);
            float2 x0 = *(const float2*)&Xs[(rb + 0) * KS + 2 * kp];
            float2 x1 = *(const float2*)&Xs[(rb + 1) * KS + 2 * kp];
            float2 x2 = *(const float2*)&Xs[(rb + 2) * KS + 2 * kp];
            float2 x3 = *(const float2*)&Xs[(rb + 3) * KS + 2 * kp];
            acc[0][0] = ffma2(x0, wc0, acc[0][0]);
            acc[0][1] = ffma2(x0, wc1, acc[0][1]);
            acc[0][2] = ffma2(x0, wc2, acc[0][2]);
            acc[0][3] = ffma2(x0, wc3, acc[0][3]);
            acc[1][0] = ffma2(x1, wc0, acc[1][0]);
            acc[1][1] = ffma2(x1, wc1, acc[1][1]);
            acc[1][2] = ffma2(x1, wc2, acc[1][2]);
            acc[1][3] = ffma2(x1, wc3, acc[1][3]);
            acc[2][0] = ffma2(x2, wc0, acc[2][0]);
            acc[2][1] = ffma2(x2, wc1, acc[2][1]);
            acc[2][2] = ffma2(x2, wc2, acc[2][2]);
            acc[2][3] = ffma2(x2, wc3, acc[2][3]);
            acc[3][0] = ffma2(x3, wc0, acc[3][0]);
            acc[3][1] = ffma2(x3, wc1, acc[3][1]);
            acc[3][2] = ffma2(x3, wc2, acc[3][2]);
            acc[3][3] = ffma2(x3, wc3, acc[3][3]);
        }

#pragma unroll
        for (int r = 0; r < 4; r++) {
            float4 o;
            o.x = acc[r][0].x + acc[r][0].y + bb.x;
            o.y = acc[r][1].x + acc[r][1].y + bb.y;
            o.z = acc[r][2].x + acc[r][2].y + bb.z;
            o.w = acc[r][3].x + acc[r][3].y + bb.w;
            if (reluOut) {
                o.x = fmaxf(o.x, 0.f); o.y = fmaxf(o.y, 0.f);
                o.z = fmaxf(o.z, 0.f); o.w = fmaxf(o.w, 0.f);
            }
            int row = t0 + rb + r;
            if (row < NN) {
                if (!fusePool) {
                    ((float4*)g_h)[((size_t)side * NN + row) * H4 + tx] = o;
                } else {
                    red4(&g_pool[side][batch[row] * HD + tx * 4], o);
                }
            }
        }
    }
}

// ---------------- final MLP ---------------------------------------------------
__global__ void k_final(const float* __restrict__ lW0, const float* __restrict__ lb0,
                        const float* __restrict__ lW1, const float* __restrict__ lb1,
                        float* __restrict__ out) {
    int g = blockIdx.x;
    int j = threadIdx.x;                                 // 96 threads
    __shared__ float cat[2 * HD + 2 * FIN];              // 320
    __shared__ float red[HD];
    for (int i = j; i < 2 * HD + 2 * FIN; i += HD) {
        float v;
        if (i < HD)            v = g_pool[0][g * HD + i] / fmaxf((float)g_cnt[0][g], 1.f);
        else if (i < 2 * HD)   v = g_pool[1][g * HD + (i - HD)] / fmaxf((float)g_cnt[1][g], 1.f);
        else if (i < 2 * HD + FIN) v = g_att[0][g * FIN + (i - 2 * HD)];
        else                   v = g_att[1][g * FIN + (i - 2 * HD - FIN)];
        cat[i] = v;
    }
    __syncthreads();
    float acc = lb0[j];
#pragma unroll 8
    for (int i = 0; i < 2 * HD + 2 * FIN; i++)
        acc += cat[i] * lW0[i * HD + j];
    red[j] = fmaxf(acc, 0.f) * lW1[j];
    __syncthreads();
    if (j == 0) {
        float s = lb1[0];
        for (int t = 0; t < HD; t++) s += red[t];
        out[g] = s;
    }
}

// ---------------- host launcher ----------------------------------------------
extern "C" void kernel_launch(void* const* d_in, const int* in_sizes, int n_in,
                              void* d_out, int out_size) {
    const float* xp  = (const float*)d_in[0];
    const float* xd  = (const float*)d_in[1];
    const int*   eip = (const int*)d_in[4];
    const int*   eid = (const int*)d_in[5];
    const int*   bp  = (const int*)d_in[6];
    const int*   bd  = (const int*)d_in[7];
    const float* Wp0 = (const float*)d_in[8],  *bp0 = (const float*)d_in[9];
    const float* Wp1 = (const float*)d_in[10], *bp1 = (const float*)d_in[11];
    const float* Wp2 = (const float*)d_in[12], *bp2 = (const float*)d_in[13];
    const float* Wd0 = (const float*)d_in[14], *bd0 = (const float*)d_in[15];
    const float* Wd1 = (const float*)d_in[16], *bd1 = (const float*)d_in[17];
    const float* Wd2 = (const float*)d_in[18], *bd2 = (const float*)d_in[19];
    const float* gW1 = (const float*)d_in[20], *gb1 = (const float*)d_in[21];
    const float* gW2 = (const float*)d_in[22], *gb2 = (const float*)d_in[23];
    const float* lW0 = (const float*)d_in[24], *lb0 = (const float*)d_in[25];
    const float* lW1 = (const float*)d_in[26], *lb1 = (const float*)d_in[27];

    const int TB = 256;
    const int GB_N2 = (NN2 + TB - 1) / TB;          // 391
    const int GB_E2 = (NE2 + TB - 1) / TB;          // 6250
    const int GB_G16 = (NN2 * 16 + TB - 1) / TB;    // 6250
    const int GB_G24 = (NN2 * 24 + TB - 1) / TB;    // 9375
    const int GEMM_GRID = 1184;                     // 592 per side
    dim3 gemmBlk(24, 6);

    k_init<<<GB_N2, TB>>>();
    k_deg<<<GB_E2, TB>>>(eip, eid);
    k_scan1<<<NSCB2, SCB>>>();
    k_scan2<<<1, 256>>>();
    k_scan3<<<NSCB2, SCB>>>();
    k_csrfill<<<GB_E2, TB>>>(eip, eid);

    k_gate<<<(NN2 + 7) / 8, 256>>>(xp, xd, bp, bd, gW1, gb1, gW2, gb2);
    k_attpool<<<GB_G16, TB>>>(xp, xd, bp, bd);

    // layer 0: gather x (K=64) -> agg; GEMM 64->96 (+relu) -> g_h
    k_gather<<<GB_G16, TB>>>((const float4*)xp, (const float4*)xd, 0, 16);
    k_gemm<<<GEMM_GRID, gemmBlk>>>(Wp0, Wd0, bp0, bd0, 16, 1, 0, bp, bd);
    // layer 1: gather g_h (K=96) -> agg; GEMM 96->96 (+relu) -> g_h
    k_gather<<<GB_G24, TB>>>(nullptr, nullptr, 1, 24);
    k_gemm<<<GEMM_GRID, gemmBlk>>>(Wp1, Wd1, bp1, bd1, 24, 1, 0, bp, bd);
    // layer 2: gather g_h -> agg; GEMM 96->96 fused with mean-pool sums
    k_gather<<<GB_G24, TB>>>(nullptr, nullptr, 1, 24);
    k_gemm<<<GEMM_GRID, gemmBlk>>>(Wp2, Wd2, bp2, bd2, 24, 0, 1, bp, bd);

    k_final<<<NG, HD>>>(lW0, lb0, lW1, lb1, (float*)d_out);
}

// round 7
// speedup vs baseline: 1.4074x; 1.0830x over previous
#include <cuda_runtime.h>
#include <cuda_fp16.h>
#include <math.h>

#define NN 50000
#define NN2 100000
#define NE 800000
#define NE2 1600000
#define FIN 64
#define HD 96
#define H4 24        // HD / 4
#define NG 256
#define GROWS 24
#define SCB 512
#define NSCB2 ((NN2 + SCB - 1) / SCB)   // 196

// ---------------- scratch (device globals; no runtime allocation) -----------
__device__ __align__(16) __half g_hh[NN2 * HD];   // layer outputs, fp16 (both sides)
__device__ __align__(16) __half g_xh[NN2 * FIN];  // input features, fp16
__device__ __align__(16) float g_agg[NN2 * HD];   // gather outputs, fp32
__device__ float g_dinv[NN2];
__device__ int   g_deg[NN2];
__device__ int   g_coff[NN2 + 1];
__device__ int   g_cur[NN2];
__device__ __align__(8) int2 g_edge[NE2];         // (local src, norm-bits)
__device__ int   g_bsum[256];
__device__ float g_gate[NN2];
__device__ float g_gden[2][NG];
__device__ __align__(16) float g_att[2][NG * FIN];
__device__ __align__(16) float g_pool[2][NG * HD];
__device__ int   g_cnt[2][NG];

// ---------------- helpers ----------------------------------------------------
__device__ __forceinline__ void red4(float* p, float4 v) {
    asm volatile("red.global.add.v4.f32 [%0], {%1,%2,%3,%4};"
                 :: "l"(p), "f"(v.x), "f"(v.y), "f"(v.z), "f"(v.w) : "memory");
}

union F2U { float2 f; unsigned long long u; };
__device__ __forceinline__ float2 ffma2(float2 a, float2 b, float2 c) {
    F2U ua, ub, uc, ud;
    ua.f = a; ub.f = b; uc.f = c;
    asm("fma.rn.f32x2 %0, %1, %2, %3;"
        : "=l"(ud.u) : "l"(ua.u), "l"(ub.u), "l"(uc.u));
    return ud.f;
}

// acc[0..7] += w * (8 halves in raw)
__device__ __forceinline__ void fma8(int4 raw, float w, float* acc) {
    __half2* h = reinterpret_cast<__half2*>(&raw);
#pragma unroll
    for (int i = 0; i < 4; i++) {
        float2 f = __half22float2(h[i]);
        acc[2 * i]     += w * f.x;
        acc[2 * i + 1] += w * f.y;
    }
}

// ---------------- init ---------------------------------------------------------
__global__ void k_init() {
    int i = blockIdx.x * blockDim.x + threadIdx.x;
    if (i < NN2) g_deg[i] = 0;
    if (i < NG) {
        g_gden[0][i] = 0.f; g_gden[1][i] = 0.f;
        g_cnt[0][i] = 0;    g_cnt[1][i] = 0;
    }
    if (i < NG * FIN) { g_att[0][i] = 0.f; g_att[1][i] = 0.f; }
    if (i < NG * HD)  { g_pool[0][i] = 0.f; g_pool[1][i] = 0.f; }
}

// convert x (both sides) to fp16
__global__ void k_tohalf(const float4* __restrict__ xp, const float4* __restrict__ xd) {
    int idx = blockIdx.x * blockDim.x + threadIdx.x;      // NN2 * 16
    if (idx >= NN2 * 16) return;
    int n = idx >> 4;
    int side = (n >= NN);
    int nl = n - side * NN;
    float4 v = __ldg(&(side ? xd : xp)[nl * 16 + (idx & 15)]);
    __half2 h0 = __floats2half2_rn(v.x, v.y);
    __half2 h1 = __floats2half2_rn(v.z, v.w);
    uint2 u;
    u.x = *(unsigned*)&h0; u.y = *(unsigned*)&h1;
    ((uint2*)g_xh)[idx] = u;
}

__global__ void k_deg(const int* __restrict__ eip, const int* __restrict__ eid) {
    int e = blockIdx.x * blockDim.x + threadIdx.x;
    if (e >= NE2) return;
    int side = (e >= NE);
    int el = e - side * NE;
    const int* ei = side ? eid : eip;
    atomicAdd(&g_deg[side * NN + ei[NE + el]], 1);
}

// ---------------- CSR build ----------------------------------------------------
__global__ void k_scan1() {
    __shared__ int s[SCB];
    int i = blockIdx.x * SCB + threadIdx.x;
    s[threadIdx.x] = (i < NN2) ? g_deg[i] : 0;
    __syncthreads();
    for (int o = SCB / 2; o > 0; o >>= 1) {
        if (threadIdx.x < o) s[threadIdx.x] += s[threadIdx.x + o];
        __syncthreads();
    }
    if (threadIdx.x == 0) g_bsum[blockIdx.x] = s[0];
}

__global__ void k_scan2() {
    __shared__ int s[256];
    int t = threadIdx.x;
    int v = (t < NSCB2) ? g_bsum[t] : 0;
    s[t] = v;
    __syncthreads();
    for (int o = 1; o < 256; o <<= 1) {
        int a = (t >= o) ? s[t - o] : 0;
        __syncthreads();
        s[t] += a;
        __syncthreads();
    }
    if (t < NSCB2) g_bsum[t] = s[t] - v;        // exclusive
    if (t == 255) g_coff[NN2] = s[255];
}

__global__ void k_scan3() {
    __shared__ int s[SCB];
    int i = blockIdx.x * SCB + threadIdx.x;
    int t = threadIdx.x;
    int v = (i < NN2) ? g_deg[i] : 0;
    s[t] = v;
    __syncthreads();
    for (int o = 1; o < SCB; o <<= 1) {
        int a = (t >= o) ? s[t - o] : 0;
        __syncthreads();
        s[t] += a;
        __syncthreads();
    }
    if (i < NN2) {
        int off = g_bsum[blockIdx.x] + s[t] - v;
        g_coff[i] = off;
        g_cur[i] = off;
        g_dinv[i] = rsqrtf((float)v + 1.0f);
    }
}

__global__ void k_csrfill(const int* __restrict__ eip, const int* __restrict__ eid) {
    int e = blockIdx.x * blockDim.x + threadIdx.x;
    if (e >= NE2) return;
    int side = (e >= NE);
    int el = e - side * NE;
    const int* ei = side ? eid : eip;
    int s = ei[el], d = ei[NE + el];
    int base = side * NN;
    float norm = g_dinv[base + s] * g_dinv[base + d];
    int slot = atomicAdd(&g_cur[base + d], 1);
    g_edge[slot] = make_int2(s, __float_as_int(norm));
}

// ---------------- attention gate (both sides) ----------------------------------
__global__ void k_gate(const float* __restrict__ xp, const float* __restrict__ xd,
                       const int* __restrict__ bp, const int* __restrict__ bd,
                       const float* __restrict__ gW1, const float* __restrict__ gb1,
                       const float* __restrict__ gW2, const float* __restrict__ gb2) {
    int lane = threadIdx.x & 31;
    int n = blockIdx.x * (blockDim.x >> 5) + (threadIdx.x >> 5);
    if (n >= NN2) return;
    int side = (n >= NN);
    int nl = n - side * NN;
    const float* x = side ? xd : xp;
    const int* batch = side ? bd : bp;
    float xa = x[nl * FIN + lane];
    float xb = x[nl * FIN + 32 + lane];
    float acc0 = gb1[lane];
    float acc1 = gb1[lane + 32];
#pragma unroll
    for (int k = 0; k < FIN; k++) {
        float xk = __shfl_sync(0xffffffffu, (k < 32) ? xa : xb, k & 31);
        acc0 += xk * gW1[k * FIN + lane];
        acc1 += xk * gW1[k * FIN + lane + 32];
    }
    float h = fmaxf(acc0, 0.f) * gW2[lane] + fmaxf(acc1, 0.f) * gW2[lane + 32];
#pragma unroll
    for (int o = 16; o > 0; o >>= 1) h += __shfl_down_sync(0xffffffffu, h, o);
    if (lane == 0) {
        float e = expf(h + gb2[0]);        // gates tiny: no max-shift needed
        g_gate[n] = e;
        int b = batch[nl];
        atomicAdd(&g_gden[side][b], e);
        atomicAdd(&g_cnt[side][b], 1);
    }
}

__global__ void k_attpool(const float* __restrict__ xp, const float* __restrict__ xd,
                          const int* __restrict__ bp, const int* __restrict__ bd) {
    int idx = blockIdx.x * blockDim.x + threadIdx.x;     // NN2 * 16
    if (idx >= NN2 * (FIN / 4)) return;
    int n = idx >> 4, j = idx & 15;
    int side = (n >= NN);
    int nl = n - side * NN;
    int b = side ? bd[nl] : bp[nl];
    float alpha = g_gate[n] / g_gden[side][b];
    const float4* x4 = side ? (const float4*)xd : (const float4*)xp;
    float4 v = __ldg(&x4[nl * (FIN / 4) + j]);
    v.x *= alpha; v.y *= alpha; v.z *= alpha; v.w *= alpha;
    red4(&g_att[side][b * FIN + j * 4], v);
}

// ---------------- fp16 CSR gather: g_agg[n] = dinv^2*f[n] + sum norm*f[src] -----
// f stored fp16, global node index rows of K8*8 halves; accumulation fp32.
__global__ void k_gatherh(const int4* __restrict__ f16, int K8) {
    int idx = blockIdx.x * blockDim.x + threadIdx.x;
    if (idx >= NN2 * K8) return;
    int n = idx / K8, j = idx - n * K8;
    int base = (n >= NN) ? NN : 0;
    float dv = g_dinv[n];
    float acc[8] = {0.f, 0.f, 0.f, 0.f, 0.f, 0.f, 0.f, 0.f};
    fma8(__ldg(&f16[(size_t)n * K8 + j]), dv * dv, acc);
    int p = __ldg(&g_coff[n]);
    int end = __ldg(&g_coff[n + 1]);
    for (; p + 1 < end; p += 2) {
        int2 e0 = __ldg(&g_edge[p]);
        int2 e1 = __ldg(&g_edge[p + 1]);
        int4 a = __ldg(&f16[(size_t)(base + e0.x) * K8 + j]);
        int4 b = __ldg(&f16[(size_t)(base + e1.x) * K8 + j]);
        fma8(a, __int_as_float(e0.y), acc);
        fma8(b, __int_as_float(e1.y), acc);
    }
    if (p < end) {
        int2 e0 = __ldg(&g_edge[p]);
        fma8(__ldg(&f16[(size_t)(base + e0.x) * K8 + j]), __int_as_float(e0.y), acc);
    }
    float4* o4 = (float4*)g_agg;
    o4[idx * 2]     = make_float4(acc[0], acc[1], acc[2], acc[3]);
    o4[idx * 2 + 1] = make_float4(acc[4], acc[5], acc[6], acc[7]);
}

// ---------------- GEMM (both sides, f32x2 FMA): out = g_agg @ W + b ------------
// Output: fp16 to g_hh (reluOut), or fp32 pool reduction (fusePool).
__global__ void __launch_bounds__(144) k_gemm(
        const float* __restrict__ Wp, const float* __restrict__ Wd,
        const float* __restrict__ bp, const float* __restrict__ bd,
        int K4, int reluOut, int fusePool,
        const int* __restrict__ batch_p, const int* __restrict__ batch_d) {
    const int K = K4 * 4;
    const int KP = K4 * 2;          // k-pairs
    const int KS = K + 4;
    __shared__ __align__(16) float Ws2[48 * 192];
    __shared__ __align__(16) float Xs[GROWS * 100];
    const int side = blockIdx.x & 1;
    const int blk = blockIdx.x >> 1;
    const int nblk = gridDim.x >> 1;
    const float* W = side ? Wd : Wp;
    const float* bias = side ? bd : bp;
    const int* batch = side ? batch_d : batch_p;
    const float4* X4 = ((const float4*)g_agg) + (size_t)side * NN * K4;
    const int tx = threadIdx.x, ty = threadIdx.y;
    const int tid = ty * 24 + tx;

    for (int i = tid; i < K * HD; i += 144) {
        int k = i / HD, c = i - k * HD;
        Ws2[(k >> 1) * 192 + c * 2 + (k & 1)] = W[i];
    }
    float4 bb = __ldg(&((const float4*)bias)[tx]);
    const int rb = ty * 4;
    const float4* W4 = (const float4*)Ws2;

    for (int t0 = blk * GROWS; t0 < NN; t0 += nblk * GROWS) {
        __syncthreads();
        for (int i = tid; i < GROWS * K4; i += 144) {
            int r = i / K4, c4 = i - r * K4;
            int row = t0 + r;
            float4 v = (row < NN) ? __ldg(&X4[(size_t)row * K4 + c4])
                                  : make_float4(0.f, 0.f, 0.f, 0.f);
            *(float4*)&Xs[r * KS + c4 * 4] = v;
        }
        __syncthreads();

        float2 acc[4][4];
#pragma unroll
        for (int r = 0; r < 4; r++)
#pragma unroll
            for (int c = 0; c < 4; c++) acc[r][c] = make_float2(0.f, 0.f);

        for (int kp = 0; kp < KP; kp++) {
            float4 wA = W4[kp * 48 + tx * 2];
            float4 wB = W4[kp * 48 + tx * 2 + 1];
            float2 wc0 = make_float2(wA.x, wA.y);
            float2 wc1 = make_float2(wA.z, wA.w);
            float2 wc2 = make_float2(wB.x, wB.y);
            float2 wc3 = make_float2(wB.z, wB.w);
            float2 x0 = *(const float2*)&Xs[(rb + 0) * KS + 2 * kp];
            float2 x1 = *(const float2*)&Xs[(rb + 1) * KS + 2 * kp];
            float2 x2 = *(const float2*)&Xs[(rb + 2) * KS + 2 * kp];
            float2 x3 = *(const float2*)&Xs[(rb + 3) * KS + 2 * kp];
            acc[0][0] = ffma2(x0, wc0, acc[0][0]);
            acc[0][1] = ffma2(x0, wc1, acc[0][1]);
            acc[0][2] = ffma2(x0, wc2, acc[0][2]);
            acc[0][3] = ffma2(x0, wc3, acc[0][3]);
            acc[1][0] = ffma2(x1, wc0, acc[1][0]);
            acc[1][1] = ffma2(x1, wc1, acc[1][1]);
            acc[1][2] = ffma2(x1, wc2, acc[1][2]);
            acc[1][3] = ffma2(x1, wc3, acc[1][3]);
            acc[2][0] = ffma2(x2, wc0, acc[2][0]);
            acc[2][1] = ffma2(x2, wc1, acc[2][1]);
            acc[2][2] = ffma2(x2, wc2, acc[2][2]);
            acc[2][3] = ffma2(x2, wc3, acc[2][3]);
            acc[3][0] = ffma2(x3, wc0, acc[3][0]);
            acc[3][1] = ffma2(x3, wc1, acc[3][1]);
            acc[3][2] = ffma2(x3, wc2, acc[3][2]);
            acc[3][3] = ffma2(x3, wc3, acc[3][3]);
        }

#pragma unroll
        for (int r = 0; r < 4; r++) {
            float4 o;
            o.x = acc[r][0].x + acc[r][0].y + bb.x;
            o.y = acc[r][1].x + acc[r][1].y + bb.y;
            o.z = acc[r][2].x + acc[r][2].y + bb.z;
            o.w = acc[r][3].x + acc[r][3].y + bb.w;
            int row = t0 + rb + r;
            if (row < NN) {
                if (!fusePool) {
                    if (reluOut) {
                        o.x = fmaxf(o.x, 0.f); o.y = fmaxf(o.y, 0.f);
                        o.z = fmaxf(o.z, 0.f); o.w = fmaxf(o.w, 0.f);
                    }
                    __half2 h0 = __floats2half2_rn(o.x, o.y);
                    __half2 h1 = __floats2half2_rn(o.z, o.w);
                    uint2 u;
                    u.x = *(unsigned*)&h0; u.y = *(unsigned*)&h1;
                    ((uint2*)g_hh)[((size_t)side * NN + row) * H4 + tx] = u;
                } else {
                    red4(&g_pool[side][batch[row] * HD + tx * 4], o);
                }
            }
        }
    }
}

// ---------------- final MLP ---------------------------------------------------
__global__ void k_final(const float* __restrict__ lW0, const float* __restrict__ lb0,
                        const float* __restrict__ lW1, const float* __restrict__ lb1,
                        float* __restrict__ out) {
    int g = blockIdx.x;
    int j = threadIdx.x;                                 // 96 threads
    __shared__ float cat[2 * HD + 2 * FIN];              // 320
    __shared__ float red[HD];
    for (int i = j; i < 2 * HD + 2 * FIN; i += HD) {
        float v;
        if (i < HD)            v = g_pool[0][g * HD + i] / fmaxf((float)g_cnt[0][g], 1.f);
        else if (i < 2 * HD)   v = g_pool[1][g * HD + (i - HD)] / fmaxf((float)g_cnt[1][g], 1.f);
        else if (i < 2 * HD + FIN) v = g_att[0][g * FIN + (i - 2 * HD)];
        else                   v = g_att[1][g * FIN + (i - 2 * HD - FIN)];
        cat[i] = v;
    }
    __syncthreads();
    float acc = lb0[j];
#pragma unroll 8
    for (int i = 0; i < 2 * HD + 2 * FIN; i++)
        acc += cat[i] * lW0[i * HD + j];
    red[j] = fmaxf(acc, 0.f) * lW1[j];
    __syncthreads();
    if (j == 0) {
        float s = lb1[0];
        for (int t = 0; t < HD; t++) s += red[t];
        out[g] = s;
    }
}

// ---------------- host launcher ----------------------------------------------
extern "C" void kernel_launch(void* const* d_in, const int* in_sizes, int n_in,
                              void* d_out, int out_size) {
    const float* xp  = (const float*)d_in[0];
    const float* xd  = (const float*)d_in[1];
    const int*   eip = (const int*)d_in[4];
    const int*   eid = (const int*)d_in[5];
    const int*   bp  = (const int*)d_in[6];
    const int*   bd  = (const int*)d_in[7];
    const float* Wp0 = (const float*)d_in[8],  *bp0 = (const float*)d_in[9];
    const float* Wp1 = (const float*)d_in[10], *bp1 = (const float*)d_in[11];
    const float* Wp2 = (const float*)d_in[12], *bp2 = (const float*)d_in[13];
    const float* Wd0 = (const float*)d_in[14], *bd0 = (const float*)d_in[15];
    const float* Wd1 = (const float*)d_in[16], *bd1 = (const float*)d_in[17];
    const float* Wd2 = (const float*)d_in[18], *bd2 = (const float*)d_in[19];
    const float* gW1 = (const float*)d_in[20], *gb1 = (const float*)d_in[21];
    const float* gW2 = (const float*)d_in[22], *gb2 = (const float*)d_in[23];
    const float* lW0 = (const float*)d_in[24], *lb0 = (const float*)d_in[25];
    const float* lW1 = (const float*)d_in[26], *lb1 = (const float*)d_in[27];

    const int TB = 256;
    const int GB_N2 = (NN2 + TB - 1) / TB;
    const int GB_E2 = (NE2 + TB - 1) / TB;
    const int GB_C16 = (NN2 * 16 + TB - 1) / TB;
    const int GB_H8  = (NN2 * 8 + TB - 1) / TB;     // layer-0 gather (K8=8)
    const int GB_H12 = (NN2 * 12 + TB - 1) / TB;    // layer-1/2 gather (K8=12)
    const int GEMM_GRID = 1184;
    dim3 gemmBlk(24, 6);

    // g_xh / g_hh device addresses for gather (resolved device-side via symbols)
    k_init<<<GB_N2, TB>>>();
    k_tohalf<<<GB_C16, TB>>>((const float4*)xp, (const float4*)xd);
    k_deg<<<GB_E2, TB>>>(eip, eid);
    k_scan1<<<NSCB2, SCB>>>();
    k_scan2<<<1, 256>>>();
    k_scan3<<<NSCB2, SCB>>>();
    k_csrfill<<<GB_E2, TB>>>(eip, eid);

    k_gate<<<(NN2 + 7) / 8, 256>>>(xp, xd, bp, bd, gW1, gb1, gW2, gb2);
    k_attpool<<<GB_C16, TB>>>(xp, xd, bp, bd);

    // device symbol addresses (host-side cudaGetSymbolAddress is not capture-hostile;
    // but simplest: pass via small launch that uses symbols directly)
    void* xh_dev = nullptr; cudaGetSymbolAddress(&xh_dev, g_xh);
    void* hh_dev = nullptr; cudaGetSymbolAddress(&hh_dev, g_hh);

    // layer 0: gather x16 (K=64) -> agg; GEMM 64->96 (+relu) -> g_hh
    k_gatherh<<<GB_H8, TB>>>((const int4*)xh_dev, 8);
    k_gemm<<<GEMM_GRID, gemmBlk>>>(Wp0, Wd0, bp0, bd0, 16, 1, 0, bp, bd);
    // layer 1: gather g_hh (K=96) -> agg; GEMM 96->96 (+relu) -> g_hh
    k_gatherh<<<GB_H12, TB>>>((const int4*)hh_dev, 12);
    k_gemm<<<GEMM_GRID, gemmBlk>>>(Wp1, Wd1, bp1, bd1, 24, 1, 0, bp, bd);
    // layer 2: gather g_hh -> agg; GEMM 96->96 fused with mean-pool sums
    k_gatherh<<<GB_H12, TB>>>((const int4*)hh_dev, 12);
    k_gemm<<<GEMM_GRID, gemmBlk>>>(Wp2, Wd2, bp2, bd2, 24, 0, 1, bp, bd);

    k_final<<<NG, HD>>>(lW0, lb0, lW1, lb1, (float*)d_out);
}

// round 8
// speedup vs baseline: 1.9042x; 1.3530x over previous
#include <cuda_runtime.h>
#include <cuda_fp16.h>
#include <math.h>

#define NN 50000
#define NN2 100000
#define NE 800000
#define NE2 1600000
#define FIN 64
#define HD 96
#define NG 256
#define SCB 512
#define NSCB2 ((NN2 + SCB - 1) / SCB)   // 196

// ---------------- scratch (device globals; no runtime allocation) -----------
__device__ __align__(16) __half g_hh[NN2 * HD];   // layer outputs, fp16
__device__ __align__(16) __half g_xh[NN2 * FIN];  // input features, fp16
__device__ __align__(16) __half g_aggh[NN2 * HD]; // gather outputs, fp16
__device__ float g_dinv[NN2];
__device__ int   g_deg[NN2];
__device__ int   g_coff[NN2 + 1];
__device__ int   g_cur[NN2];
__device__ __align__(8) int2 g_edge[NE2];         // (local src, norm-bits)
__device__ int   g_bsum[256];
__device__ float g_gate[NN2];
__device__ float g_gden[2][NG];
__device__ __align__(16) float g_att[2][NG * FIN];
__device__ __align__(16) float g_pool[2][NG * HD];
__device__ int   g_cnt[2][NG];

// ---------------- helpers ----------------------------------------------------
__device__ __forceinline__ void red4(float* p, float4 v) {
    asm volatile("red.global.add.v4.f32 [%0], {%1,%2,%3,%4};"
                 :: "l"(p), "f"(v.x), "f"(v.y), "f"(v.z), "f"(v.w) : "memory");
}
__device__ __forceinline__ void red2(float* p, float a, float b) {
    asm volatile("red.global.add.v2.f32 [%0], {%1,%2};"
                 :: "l"(p), "f"(a), "f"(b) : "memory");
}

__device__ __forceinline__ void mma16816(float* c, const unsigned* a, unsigned b0, unsigned b1) {
    asm volatile(
        "mma.sync.aligned.m16n8k16.row.col.f32.f16.f16.f32 "
        "{%0,%1,%2,%3}, {%4,%5,%6,%7}, {%8,%9}, {%0,%1,%2,%3};"
        : "+f"(c[0]), "+f"(c[1]), "+f"(c[2]), "+f"(c[3])
        : "r"(a[0]), "r"(a[1]), "r"(a[2]), "r"(a[3]), "r"(b0), "r"(b1));
}

// acc[0..7] += w * (8 halves in raw)
__device__ __forceinline__ void fma8(int4 raw, float w, float* acc) {
    __half2* h = reinterpret_cast<__half2*>(&raw);
#pragma unroll
    for (int i = 0; i < 4; i++) {
        float2 f = __half22float2(h[i]);
        acc[2 * i]     += w * f.x;
        acc[2 * i + 1] += w * f.y;
    }
}

// ---------------- init ---------------------------------------------------------
__global__ void k_init() {
    int i = blockIdx.x * blockDim.x + threadIdx.x;
    if (i < NN2) g_deg[i] = 0;
    if (i < NG) {
        g_gden[0][i] = 0.f; g_gden[1][i] = 0.f;
        g_cnt[0][i] = 0;    g_cnt[1][i] = 0;
    }
    if (i < NG * FIN) { g_att[0][i] = 0.f; g_att[1][i] = 0.f; }
    if (i < NG * HD)  { g_pool[0][i] = 0.f; g_pool[1][i] = 0.f; }
}

__global__ void k_tohalf(const float4* __restrict__ xp, const float4* __restrict__ xd) {
    int idx = blockIdx.x * blockDim.x + threadIdx.x;      // NN2 * 16
    if (idx >= NN2 * 16) return;
    int n = idx >> 4;
    int side = (n >= NN);
    int nl = n - side * NN;
    float4 v = __ldg(&(side ? xd : xp)[nl * 16 + (idx & 15)]);
    __half2 h0 = __floats2half2_rn(v.x, v.y);
    __half2 h1 = __floats2half2_rn(v.z, v.w);
    uint2 u;
    u.x = *(unsigned*)&h0; u.y = *(unsigned*)&h1;
    ((uint2*)g_xh)[idx] = u;
}

__global__ void k_deg(const int* __restrict__ eip, const int* __restrict__ eid) {
    int e = blockIdx.x * blockDim.x + threadIdx.x;
    if (e >= NE2) return;
    int side = (e >= NE);
    int el = e - side * NE;
    const int* ei = side ? eid : eip;
    atomicAdd(&g_deg[side * NN + ei[NE + el]], 1);
}

// ---------------- CSR build ----------------------------------------------------
__global__ void k_scan1() {
    __shared__ int s[SCB];
    int i = blockIdx.x * SCB + threadIdx.x;
    s[threadIdx.x] = (i < NN2) ? g_deg[i] : 0;
    __syncthreads();
    for (int o = SCB / 2; o > 0; o >>= 1) {
        if (threadIdx.x < o) s[threadIdx.x] += s[threadIdx.x + o];
        __syncthreads();
    }
    if (threadIdx.x == 0) g_bsum[blockIdx.x] = s[0];
}

__global__ void k_scan2() {
    __shared__ int s[256];
    int t = threadIdx.x;
    int v = (t < NSCB2) ? g_bsum[t] : 0;
    s[t] = v;
    __syncthreads();
    for (int o = 1; o < 256; o <<= 1) {
        int a = (t >= o) ? s[t - o] : 0;
        __syncthreads();
        s[t] += a;
        __syncthreads();
    }
    if (t < NSCB2) g_bsum[t] = s[t] - v;
    if (t == 255) g_coff[NN2] = s[255];
}

__global__ void k_scan3() {
    __shared__ int s[SCB];
    int i = blockIdx.x * SCB + threadIdx.x;
    int t = threadIdx.x;
    int v = (i < NN2) ? g_deg[i] : 0;
    s[t] = v;
    __syncthreads();
    for (int o = 1; o < SCB; o <<= 1) {
        int a = (t >= o) ? s[t - o] : 0;
        __syncthreads();
        s[t] += a;
        __syncthreads();
    }
    if (i < NN2) {
        int off = g_bsum[blockIdx.x] + s[t] - v;
        g_coff[i] = off;
        g_cur[i] = off;
        g_dinv[i] = rsqrtf((float)v + 1.0f);
    }
}

__global__ void k_csrfill(const int* __restrict__ eip, const int* __restrict__ eid) {
    int e = blockIdx.x * blockDim.x + threadIdx.x;
    if (e >= NE2) return;
    int side = (e >= NE);
    int el = e - side * NE;
    const int* ei = side ? eid : eip;
    int s = ei[el], d = ei[NE + el];
    int base = side * NN;
    float norm = g_dinv[base + s] * g_dinv[base + d];
    int slot = atomicAdd(&g_cur[base + d], 1);
    g_edge[slot] = make_int2(s, __float_as_int(norm));
}

// ---------------- attention gate (both sides) ----------------------------------
__global__ void k_gate(const float* __restrict__ xp, const float* __restrict__ xd,
                       const int* __restrict__ bp, const int* __restrict__ bd,
                       const float* __restrict__ gW1, const float* __restrict__ gb1,
                       const float* __restrict__ gW2, const float* __restrict__ gb2) {
    int lane = threadIdx.x & 31;
    int n = blockIdx.x * (blockDim.x >> 5) + (threadIdx.x >> 5);
    if (n >= NN2) return;
    int side = (n >= NN);
    int nl = n - side * NN;
    const float* x = side ? xd : xp;
    const int* batch = side ? bd : bp;
    float xa = x[nl * FIN + lane];
    float xb = x[nl * FIN + 32 + lane];
    float acc0 = gb1[lane];
    float acc1 = gb1[lane + 32];
#pragma unroll
    for (int k = 0; k < FIN; k++) {
        float xk = __shfl_sync(0xffffffffu, (k < 32) ? xa : xb, k & 31);
        acc0 += xk * gW1[k * FIN + lane];
        acc1 += xk * gW1[k * FIN + lane + 32];
    }
    float h = fmaxf(acc0, 0.f) * gW2[lane] + fmaxf(acc1, 0.f) * gW2[lane + 32];
#pragma unroll
    for (int o = 16; o > 0; o >>= 1) h += __shfl_down_sync(0xffffffffu, h, o);
    if (lane == 0) {
        float e = expf(h + gb2[0]);        // gates tiny: no max-shift needed
        g_gate[n] = e;
        int b = batch[nl];
        atomicAdd(&g_gden[side][b], e);
        atomicAdd(&g_cnt[side][b], 1);
    }
}

__global__ void k_attpool(const float* __restrict__ xp, const float* __restrict__ xd,
                          const int* __restrict__ bp, const int* __restrict__ bd) {
    int idx = blockIdx.x * blockDim.x + threadIdx.x;     // NN2 * 16
    if (idx >= NN2 * (FIN / 4)) return;
    int n = idx >> 4, j = idx & 15;
    int side = (n >= NN);
    int nl = n - side * NN;
    int b = side ? bd[nl] : bp[nl];
    float alpha = g_gate[n] / g_gden[side][b];
    const float4* x4 = side ? (const float4*)xd : (const float4*)xp;
    float4 v = __ldg(&x4[nl * (FIN / 4) + j]);
    v.x *= alpha; v.y *= alpha; v.z *= alpha; v.w *= alpha;
    red4(&g_att[side][b * FIN + j * 4], v);
}

// ---------------- fp16 CSR gather -> fp16 agg ----------------------------------
// g_aggh[n] = dinv^2*f[n] + sum norm*f[src]; fp32 accumulation, fp16 store.
__global__ void k_gatherh(const int4* __restrict__ f16, int K8) {
    int idx = blockIdx.x * blockDim.x + threadIdx.x;
    if (idx >= NN2 * K8) return;
    int n = idx / K8, j = idx - n * K8;
    int base = (n >= NN) ? NN : 0;
    float dv = g_dinv[n];
    float acc[8] = {0.f, 0.f, 0.f, 0.f, 0.f, 0.f, 0.f, 0.f};
    fma8(__ldg(&f16[(size_t)n * K8 + j]), dv * dv, acc);
    int p = __ldg(&g_coff[n]);
    int end = __ldg(&g_coff[n + 1]);
    for (; p + 1 < end; p += 2) {
        int2 e0 = __ldg(&g_edge[p]);
        int2 e1 = __ldg(&g_edge[p + 1]);
        int4 a = __ldg(&f16[(size_t)(base + e0.x) * K8 + j]);
        int4 b = __ldg(&f16[(size_t)(base + e1.x) * K8 + j]);
        fma8(a, __int_as_float(e0.y), acc);
        fma8(b, __int_as_float(e1.y), acc);
    }
    if (p < end) {
        int2 e0 = __ldg(&g_edge[p]);
        fma8(__ldg(&f16[(size_t)(base + e0.x) * K8 + j]), __int_as_float(e0.y), acc);
    }
    __half2 h0 = __floats2half2_rn(acc[0], acc[1]);
    __half2 h1 = __floats2half2_rn(acc[2], acc[3]);
    __half2 h2 = __floats2half2_rn(acc[4], acc[5]);
    __half2 h3 = __floats2half2_rn(acc[6], acc[7]);
    int4 o;
    o.x = *(int*)&h0; o.y = *(int*)&h1; o.z = *(int*)&h2; o.w = *(int*)&h3;
    ((int4*)g_aggh)[idx] = o;
}

// ---------------- HMMA GEMM: out[rows,96] = aggh[rows,K] @ W[K,96] + b ----------
// W split hi+lo fp16 (residual encoding) so fp32 weight accuracy is preserved.
// Block: 256 thr / 8 warps; 128-row tile per block; warp = 16 rows.
__global__ void __launch_bounds__(256) k_gemm_mma(
        const float* __restrict__ Wp, const float* __restrict__ Wd,
        const float* __restrict__ bp, const float* __restrict__ bd,
        int K, int reluOut, int fusePool,
        const int* __restrict__ batch_p, const int* __restrict__ batch_d) {
    extern __shared__ __half sm[];
    const int KS = K + 8;                 // half stride; (K+8)*2 bytes, 16B-mult
    __half* As  = sm;                     // 128 x KS
    __half* Bhi = As + 128 * KS;          // 96 x KS  (Bt layout: [n][k])
    __half* Blo = Bhi + 96 * KS;
    const int side = blockIdx.x & 1;
    const int tile = blockIdx.x >> 1;
    const int rowBase = tile * 128;
    const float* W = side ? Wd : Wp;
    const float* bias = side ? bd : bp;
    const int* batch = side ? batch_d : batch_p;
    const int tid = threadIdx.x;
    const int K8 = K >> 3;

    // load W -> Bt hi/lo (transpose)
    for (int i = tid; i < K * HD; i += 256) {
        int k = i / HD, n = i - k * HD;
        float w = __ldg(&W[i]);
        __half hi = __float2half_rn(w);
        __half lo = __float2half_rn(w - __half2float(hi));
        Bhi[n * KS + k] = hi;
        Blo[n * KS + k] = lo;
    }
    // load A tile (128 rows x K halves)
    const int4* Ah = (const int4*)g_aggh;
    for (int i = tid; i < 128 * K8; i += 256) {
        int r = i / K8, j = i - r * K8;
        int row = rowBase + r;
        int4 v = make_int4(0, 0, 0, 0);
        if (row < NN) v = __ldg(&Ah[(size_t)(side * NN + row) * K8 + j]);
        *(int4*)&As[r * KS + j * 8] = v;
    }
    __syncthreads();

    const int warp = tid >> 5;
    const int lane = tid & 31;
    const int g = lane >> 2;              // group id (0..7)
    const int tg = lane & 3;              // thread-in-group
    const int warpRow = warp * 16;

    float c[12][4];
#pragma unroll
    for (int nt = 0; nt < 12; nt++)
#pragma unroll
        for (int q = 0; q < 4; q++) c[nt][q] = 0.f;

    const int nk = K >> 4;
    for (int ks = 0; ks < nk; ks++) {
        unsigned a[4];
        const __half* arow0 = &As[(warpRow + g) * KS + ks * 16 + tg * 2];
        const __half* arow1 = arow0 + 8 * KS;
        a[0] = *(const unsigned*)arow0;
        a[1] = *(const unsigned*)arow1;
        a[2] = *(const unsigned*)(arow0 + 8);
        a[3] = *(const unsigned*)(arow1 + 8);
#pragma unroll
        for (int nt = 0; nt < 12; nt++) {
            const __half* brow = &Bhi[(nt * 8 + g) * KS + ks * 16 + tg * 2];
            unsigned b0 = *(const unsigned*)brow;
            unsigned b1 = *(const unsigned*)(brow + 8);
            mma16816(c[nt], a, b0, b1);
            const __half* brl = &Blo[(nt * 8 + g) * KS + ks * 16 + tg * 2];
            unsigned l0 = *(const unsigned*)brl;
            unsigned l1 = *(const unsigned*)(brl + 8);
            mma16816(c[nt], a, l0, l1);
        }
    }

    // epilogue
    int row0 = rowBase + warpRow + g;
    int row1 = row0 + 8;
#pragma unroll
    for (int nt = 0; nt < 12; nt++) {
        int col = nt * 8 + tg * 2;
        float bx = __ldg(&bias[col]);
        float by = __ldg(&bias[col + 1]);
        float v00 = c[nt][0] + bx, v01 = c[nt][1] + by;
        float v10 = c[nt][2] + bx, v11 = c[nt][3] + by;
        if (!fusePool) {
            if (reluOut) {
                v00 = fmaxf(v00, 0.f); v01 = fmaxf(v01, 0.f);
                v10 = fmaxf(v10, 0.f); v11 = fmaxf(v11, 0.f);
            }
            if (row0 < NN) {
                __half2 h = __floats2half2_rn(v00, v01);
                *(unsigned*)&g_hh[(size_t)(side * NN + row0) * HD + col] = *(unsigned*)&h;
            }
            if (row1 < NN) {
                __half2 h = __floats2half2_rn(v10, v11);
                *(unsigned*)&g_hh[(size_t)(side * NN + row1) * HD + col] = *(unsigned*)&h;
            }
        } else {
            if (row0 < NN) red2(&g_pool[side][batch[row0] * HD + col], v00, v01);
            if (row1 < NN) red2(&g_pool[side][batch[row1] * HD + col], v10, v11);
        }
    }
}

// ---------------- final MLP ---------------------------------------------------
__global__ void k_final(const float* __restrict__ lW0, const float* __restrict__ lb0,
                        const float* __restrict__ lW1, const float* __restrict__ lb1,
                        float* __restrict__ out) {
    int g = blockIdx.x;
    int j = threadIdx.x;                                 // 96 threads
    __shared__ float cat[2 * HD + 2 * FIN];              // 320
    __shared__ float red[HD];
    for (int i = j; i < 2 * HD + 2 * FIN; i += HD) {
        float v;
        if (i < HD)            v = g_pool[0][g * HD + i] / fmaxf((float)g_cnt[0][g], 1.f);
        else if (i < 2 * HD)   v = g_pool[1][g * HD + (i - HD)] / fmaxf((float)g_cnt[1][g], 1.f);
        else if (i < 2 * HD + FIN) v = g_att[0][g * FIN + (i - 2 * HD)];
        else                   v = g_att[1][g * FIN + (i - 2 * HD - FIN)];
        cat[i] = v;
    }
    __syncthreads();
    float acc = lb0[j];
#pragma unroll 8
    for (int i = 0; i < 2 * HD + 2 * FIN; i++)
        acc += cat[i] * lW0[i * HD + j];
    red[j] = fmaxf(acc, 0.f) * lW1[j];
    __syncthreads();
    if (j == 0) {
        float s = lb1[0];
        for (int t = 0; t < HD; t++) s += red[t];
        out[g] = s;
    }
}

// ---------------- host launcher ----------------------------------------------
extern "C" void kernel_launch(void* const* d_in, const int* in_sizes, int n_in,
                              void* d_out, int out_size) {
    const float* xp  = (const float*)d_in[0];
    const float* xd  = (const float*)d_in[1];
    const int*   eip = (const int*)d_in[4];
    const int*   eid = (const int*)d_in[5];
    const int*   bp  = (const int*)d_in[6];
    const int*   bd  = (const int*)d_in[7];
    const float* Wp0 = (const float*)d_in[8],  *bp0 = (const float*)d_in[9];
    const float* Wp1 = (const float*)d_in[10], *bp1 = (const float*)d_in[11];
    const float* Wp2 = (const float*)d_in[12], *bp2 = (const float*)d_in[13];
    const float* Wd0 = (const float*)d_in[14], *bd0 = (const float*)d_in[15];
    const float* Wd1 = (const float*)d_in[16], *bd1 = (const float*)d_in[17];
    const float* Wd2 = (const float*)d_in[18], *bd2 = (const float*)d_in[19];
    const float* gW1 = (const float*)d_in[20], *gb1 = (const float*)d_in[21];
    const float* gW2 = (const float*)d_in[22], *gb2 = (const float*)d_in[23];
    const float* lW0 = (const float*)d_in[24], *lb0 = (const float*)d_in[25];
    const float* lW1 = (const float*)d_in[26], *lb1 = (const float*)d_in[27];

    const int TB = 256;
    const int GB_N2 = (NN2 + TB - 1) / TB;
    const int GB_E2 = (NE2 + TB - 1) / TB;
    const int GB_C16 = (NN2 * 16 + TB - 1) / TB;
    const int GB_H8  = (NN2 * 8 + TB - 1) / TB;
    const int GB_H12 = (NN2 * 12 + TB - 1) / TB;
    const int GEMM_GRID = 782;                       // 391 tiles x 2 sides
    const int SMEM96 = (128 + 96 + 96) * (96 + 8) * 2;   // 66560 B
    const int SMEM64 = (128 + 96 + 96) * (64 + 8) * 2;   // 46080 B

    static int smemSet = 0;
    if (!smemSet) {
        cudaFuncSetAttribute(k_gemm_mma, cudaFuncAttributeMaxDynamicSharedMemorySize, SMEM96);
        smemSet = 1;
    }

    k_init<<<GB_N2, TB>>>();
    k_tohalf<<<GB_C16, TB>>>((const float4*)xp, (const float4*)xd);
    k_deg<<<GB_E2, TB>>>(eip, eid);
    k_scan1<<<NSCB2, SCB>>>();
    k_scan2<<<1, 256>>>();
    k_scan3<<<NSCB2, SCB>>>();
    k_csrfill<<<GB_E2, TB>>>(eip, eid);

    k_gate<<<(NN2 + 7) / 8, 256>>>(xp, xd, bp, bd, gW1, gb1, gW2, gb2);
    k_attpool<<<GB_C16, TB>>>(xp, xd, bp, bd);

    void* xh_dev = nullptr; cudaGetSymbolAddress(&xh_dev, g_xh);
    void* hh_dev = nullptr; cudaGetSymbolAddress(&hh_dev, g_hh);

    // layer 0: gather x (K=64) -> aggh; HMMA GEMM 64->96 (+relu) -> g_hh
    k_gatherh<<<GB_H8, TB>>>((const int4*)xh_dev, 8);
    k_gemm_mma<<<GEMM_GRID, 256, SMEM64>>>(Wp0, Wd0, bp0, bd0, 64, 1, 0, bp, bd);
    // layer 1: gather g_hh (K=96) -> aggh; HMMA GEMM 96->96 (+relu) -> g_hh
    k_gatherh<<<GB_H12, TB>>>((const int4*)hh_dev, 12);
    k_gemm_mma<<<GEMM_GRID, 256, SMEM96>>>(Wp1, Wd1, bp1, bd1, 96, 1, 0, bp, bd);
    // layer 2: gather g_hh -> aggh; HMMA GEMM 96->96 fused with mean-pool sums
    k_gatherh<<<GB_H12, TB>>>((const int4*)hh_dev, 12);
    k_gemm_mma<<<GEMM_GRID, 256, SMEM96>>>(Wp2, Wd2, bp2, bd2, 96, 0, 1, bp, bd);

    k_final<<<NG, HD>>>(lW0, lb0, lW1, lb1, (float*)d_out);
}

// round 9
// speedup vs baseline: 1.9434x; 1.0206x over previous
#include <cuda_runtime.h>
#include <cuda_fp16.h>
#include <math.h>

#define NN 50000
#define NN2 100000
#define NE 800000
#define NE2 1600000
#define FIN 64
#define HD 96
#define NG 256
#define SCB 512
#define NSCB2 ((NN2 + SCB - 1) / SCB)   // 196

// ---------------- scratch (device globals; no runtime allocation) -----------
__device__ __align__(16) __half g_hh[NN2 * HD];   // layer outputs, fp16
__device__ __align__(16) __half g_xh[NN2 * FIN];  // input features, fp16
__device__ __align__(16) __half g_aggh[NN2 * HD]; // gather outputs, fp16
__device__ float g_dinv[NN2];
__device__ int   g_deg[NN2];
__device__ int   g_coff[NN2 + 1];
__device__ int   g_cur[NN2];
__device__ __align__(8) int2 g_edge[NE2];         // (local src, norm-bits)
__device__ int   g_bsum[256];
__device__ float g_gate[NN2];

// zero-initialized-per-iteration block (single memset)
struct __align__(16) ZeroBlk {
    float gden[2][NG];
    int   cnt[2][NG];
    float att[2][NG * FIN];
    float pool[2][NG * HD];
};
__device__ ZeroBlk g_z;

// ---------------- helpers ----------------------------------------------------
__device__ __forceinline__ void red4(float* p, float4 v) {
    asm volatile("red.global.add.v4.f32 [%0], {%1,%2,%3,%4};"
                 :: "l"(p), "f"(v.x), "f"(v.y), "f"(v.z), "f"(v.w) : "memory");
}
__device__ __forceinline__ void red2(float* p, float a, float b) {
    asm volatile("red.global.add.v2.f32 [%0], {%1,%2};"
                 :: "l"(p), "f"(a), "f"(b) : "memory");
}

__device__ __forceinline__ void mma16816(float* c, const unsigned* a, unsigned b0, unsigned b1) {
    asm volatile(
        "mma.sync.aligned.m16n8k16.row.col.f32.f16.f16.f32 "
        "{%0,%1,%2,%3}, {%4,%5,%6,%7}, {%8,%9}, {%0,%1,%2,%3};"
        : "+f"(c[0]), "+f"(c[1]), "+f"(c[2]), "+f"(c[3])
        : "r"(a[0]), "r"(a[1]), "r"(a[2]), "r"(a[3]), "r"(b0), "r"(b1));
}

// acc[0..7] += w * (8 halves in raw)
__device__ __forceinline__ void fma8(int4 raw, float w, float* acc) {
    __half2* h = reinterpret_cast<__half2*>(&raw);
#pragma unroll
    for (int i = 0; i < 4; i++) {
        float2 f = __half22float2(h[i]);
        acc[2 * i]     += w * f.x;
        acc[2 * i + 1] += w * f.y;
    }
}

// ---------------- input conversion ---------------------------------------------
__global__ void k_tohalf(const float4* __restrict__ xp, const float4* __restrict__ xd) {
    int idx = blockIdx.x * blockDim.x + threadIdx.x;      // NN2 * 16
    if (idx >= NN2 * 16) return;
    int n = idx >> 4;
    int side = (n >= NN);
    int nl = n - side * NN;
    float4 v = __ldg(&(side ? xd : xp)[nl * 16 + (idx & 15)]);
    __half2 h0 = __floats2half2_rn(v.x, v.y);
    __half2 h1 = __floats2half2_rn(v.z, v.w);
    uint2 u;
    u.x = *(unsigned*)&h0; u.y = *(unsigned*)&h1;
    ((uint2*)g_xh)[idx] = u;
}

__global__ void k_deg(const int* __restrict__ eip, const int* __restrict__ eid) {
    int e = blockIdx.x * blockDim.x + threadIdx.x;
    if (e >= NE2) return;
    int side = (e >= NE);
    int el = e - side * NE;
    const int* ei = side ? eid : eip;
    atomicAdd(&g_deg[side * NN + ei[NE + el]], 1);
}

// ---------------- CSR build ----------------------------------------------------
__global__ void k_scan1() {
    __shared__ int s[SCB];
    int i = blockIdx.x * SCB + threadIdx.x;
    s[threadIdx.x] = (i < NN2) ? g_deg[i] : 0;
    __syncthreads();
    for (int o = SCB / 2; o > 0; o >>= 1) {
        if (threadIdx.x < o) s[threadIdx.x] += s[threadIdx.x + o];
        __syncthreads();
    }
    if (threadIdx.x == 0) g_bsum[blockIdx.x] = s[0];
}

// scan3: per-block offset computed in-block from g_bsum (scan2 eliminated)
__global__ void k_scan3() {
    __shared__ int sb[SCB];
    int t = threadIdx.x;
    sb[t] = (t < blockIdx.x) ? g_bsum[t] : 0;       // blockIdx.x < 196 <= SCB
    __syncthreads();
    for (int o = SCB / 2; o > 0; o >>= 1) {
        if (t < o) sb[t] += sb[t + o];
        __syncthreads();
    }
    int boff = sb[0];
    __syncthreads();
    int i = blockIdx.x * SCB + t;
    int v = (i < NN2) ? g_deg[i] : 0;
    sb[t] = v;
    __syncthreads();
    for (int o = 1; o < SCB; o <<= 1) {
        int a = (t >= o) ? sb[t - o] : 0;
        __syncthreads();
        sb[t] += a;
        __syncthreads();
    }
    if (i < NN2) {
        int off = boff + sb[t] - v;                 // exclusive
        g_coff[i] = off;
        g_cur[i] = off;
        g_dinv[i] = rsqrtf((float)v + 1.0f);
    }
    if (blockIdx.x == NSCB2 - 1 && t == SCB - 1) g_coff[NN2] = boff + sb[t];
}

__global__ void k_csrfill(const int* __restrict__ eip, const int* __restrict__ eid) {
    int e = blockIdx.x * blockDim.x + threadIdx.x;
    if (e >= NE2) return;
    int side = (e >= NE);
    int el = e - side * NE;
    const int* ei = side ? eid : eip;
    int s = ei[el], d = ei[NE + el];
    int base = side * NN;
    float norm = g_dinv[base + s] * g_dinv[base + d];
    int slot = atomicAdd(&g_cur[base + d], 1);
    g_edge[slot] = make_int2(s, __float_as_int(norm));
}

// ---------------- attention gate (both sides) ----------------------------------
__global__ void k_gate(const float* __restrict__ xp, const float* __restrict__ xd,
                       const int* __restrict__ bp, const int* __restrict__ bd,
                       const float* __restrict__ gW1, const float* __restrict__ gb1,
                       const float* __restrict__ gW2, const float* __restrict__ gb2) {
    int lane = threadIdx.x & 31;
    int n = blockIdx.x * (blockDim.x >> 5) + (threadIdx.x >> 5);
    if (n >= NN2) return;
    int side = (n >= NN);
    int nl = n - side * NN;
    const float* x = side ? xd : xp;
    const int* batch = side ? bd : bp;
    float xa = x[nl * FIN + lane];
    float xb = x[nl * FIN + 32 + lane];
    float acc0 = gb1[lane];
    float acc1 = gb1[lane + 32];
#pragma unroll
    for (int k = 0; k < FIN; k++) {
        float xk = __shfl_sync(0xffffffffu, (k < 32) ? xa : xb, k & 31);
        acc0 += xk * gW1[k * FIN + lane];
        acc1 += xk * gW1[k * FIN + lane + 32];
    }
    float h = fmaxf(acc0, 0.f) * gW2[lane] + fmaxf(acc1, 0.f) * gW2[lane + 32];
#pragma unroll
    for (int o = 16; o > 0; o >>= 1) h += __shfl_down_sync(0xffffffffu, h, o);
    if (lane == 0) {
        float e = expf(h + gb2[0]);        // gates tiny: no max-shift needed
        g_gate[n] = e;
        int b = batch[nl];
        atomicAdd(&g_z.gden[side][b], e);
        atomicAdd(&g_z.cnt[side][b], 1);
    }
}

__global__ void k_attpool(const float* __restrict__ xp, const float* __restrict__ xd,
                          const int* __restrict__ bp, const int* __restrict__ bd) {
    int idx = blockIdx.x * blockDim.x + threadIdx.x;     // NN2 * 16
    if (idx >= NN2 * (FIN / 4)) return;
    int n = idx >> 4, j = idx & 15;
    int side = (n >= NN);
    int nl = n - side * NN;
    int b = side ? bd[nl] : bp[nl];
    float alpha = g_gate[n] / g_z.gden[side][b];
    const float4* x4 = side ? (const float4*)xd : (const float4*)xp;
    float4 v = __ldg(&x4[nl * (FIN / 4) + j]);
    v.x *= alpha; v.y *= alpha; v.z *= alpha; v.w *= alpha;
    red4(&g_z.att[side][b * FIN + j * 4], v);
}

// ---------------- fp16 CSR gather -> fp16 agg ----------------------------------
__global__ void k_gatherh(const int4* __restrict__ f16, int K8) {
    int idx = blockIdx.x * blockDim.x + threadIdx.x;
    if (idx >= NN2 * K8) return;
    int n = idx / K8, j = idx - n * K8;
    int base = (n >= NN) ? NN : 0;
    float dv = g_dinv[n];
    float acc[8] = {0.f, 0.f, 0.f, 0.f, 0.f, 0.f, 0.f, 0.f};
    fma8(__ldg(&f16[(size_t)n * K8 + j]), dv * dv, acc);
    int p = __ldg(&g_coff[n]);
    int end = __ldg(&g_coff[n + 1]);
    for (; p + 1 < end; p += 2) {
        int2 e0 = __ldg(&g_edge[p]);
        int2 e1 = __ldg(&g_edge[p + 1]);
        int4 a = __ldg(&f16[(size_t)(base + e0.x) * K8 + j]);
        int4 b = __ldg(&f16[(size_t)(base + e1.x) * K8 + j]);
        fma8(a, __int_as_float(e0.y), acc);
        fma8(b, __int_as_float(e1.y), acc);
    }
    if (p < end) {
        int2 e0 = __ldg(&g_edge[p]);
        fma8(__ldg(&f16[(size_t)(base + e0.x) * K8 + j]), __int_as_float(e0.y), acc);
    }
    __half2 h0 = __floats2half2_rn(acc[0], acc[1]);
    __half2 h1 = __floats2half2_rn(acc[2], acc[3]);
    __half2 h2 = __floats2half2_rn(acc[4], acc[5]);
    __half2 h3 = __floats2half2_rn(acc[6], acc[7]);
    int4 o;
    o.x = *(int*)&h0; o.y = *(int*)&h1; o.z = *(int*)&h2; o.w = *(int*)&h3;
    ((int4*)g_aggh)[idx] = o;
}

// ---------------- HMMA GEMM: out[rows,96] = aggh[rows,K] @ W[K,96] + b ----------
__global__ void __launch_bounds__(256) k_gemm_mma(
        const float* __restrict__ Wp, const float* __restrict__ Wd,
        const float* __restrict__ bp, const float* __restrict__ bd,
        int K, int reluOut, int fusePool,
        const int* __restrict__ batch_p, const int* __restrict__ batch_d) {
    extern __shared__ __half sm[];
    const int KS = K + 8;
    __half* As  = sm;                     // 128 x KS
    __half* Bhi = As + 128 * KS;          // 96 x KS  ([n][k])
    __half* Blo = Bhi + 96 * KS;
    const int side = blockIdx.x & 1;
    const int tile = blockIdx.x >> 1;
    const int rowBase = tile * 128;
    const float* W = side ? Wd : Wp;
    const float* bias = side ? bd : bp;
    const int* batch = side ? batch_d : batch_p;
    const int tid = threadIdx.x;
    const int K8 = K >> 3;

    for (int i = tid; i < K * HD; i += 256) {
        int k = i / HD, n = i - k * HD;
        float w = __ldg(&W[i]);
        __half hi = __float2half_rn(w);
        __half lo = __float2half_rn(w - __half2float(hi));
        Bhi[n * KS + k] = hi;
        Blo[n * KS + k] = lo;
    }
    const int4* Ah = (const int4*)g_aggh;
    for (int i = tid; i < 128 * K8; i += 256) {
        int r = i / K8, j = i - r * K8;
        int row = rowBase + r;
        int4 v = make_int4(0, 0, 0, 0);
        if (row < NN) v = __ldg(&Ah[(size_t)(side * NN + row) * K8 + j]);
        *(int4*)&As[r * KS + j * 8] = v;
    }
    __syncthreads();

    const int warp = tid >> 5;
    const int lane = tid & 31;
    const int g = lane >> 2;
    const int tg = lane & 3;
    const int warpRow = warp * 16;

    float c[12][4];
#pragma unroll
    for (int nt = 0; nt < 12; nt++)
#pragma unroll
        for (int q = 0; q < 4; q++) c[nt][q] = 0.f;

    const int nk = K >> 4;
    for (int ks = 0; ks < nk; ks++) {
        unsigned a[4];
        const __half* arow0 = &As[(warpRow + g) * KS + ks * 16 + tg * 2];
        const __half* arow1 = arow0 + 8 * KS;
        a[0] = *(const unsigned*)arow0;
        a[1] = *(const unsigned*)arow1;
        a[2] = *(const unsigned*)(arow0 + 8);
        a[3] = *(const unsigned*)(arow1 + 8);
#pragma unroll
        for (int nt = 0; nt < 12; nt++) {
            const __half* brow = &Bhi[(nt * 8 + g) * KS + ks * 16 + tg * 2];
            unsigned b0 = *(const unsigned*)brow;
            unsigned b1 = *(const unsigned*)(brow + 8);
            mma16816(c[nt], a, b0, b1);
            const __half* brl = &Blo[(nt * 8 + g) * KS + ks * 16 + tg * 2];
            unsigned l0 = *(const unsigned*)brl;
            unsigned l1 = *(const unsigned*)(brl + 8);
            mma16816(c[nt], a, l0, l1);
        }
    }

    int row0 = rowBase + warpRow + g;
    int row1 = row0 + 8;
#pragma unroll
    for (int nt = 0; nt < 12; nt++) {
        int col = nt * 8 + tg * 2;
        float bx = __ldg(&bias[col]);
        float by = __ldg(&bias[col + 1]);
        float v00 = c[nt][0] + bx, v01 = c[nt][1] + by;
        float v10 = c[nt][2] + bx, v11 = c[nt][3] + by;
        if (!fusePool) {
            if (reluOut) {
                v00 = fmaxf(v00, 0.f); v01 = fmaxf(v01, 0.f);
                v10 = fmaxf(v10, 0.f); v11 = fmaxf(v11, 0.f);
            }
            if (row0 < NN) {
                __half2 h = __floats2half2_rn(v00, v01);
                *(unsigned*)&g_hh[(size_t)(side * NN + row0) * HD + col] = *(unsigned*)&h;
            }
            if (row1 < NN) {
                __half2 h = __floats2half2_rn(v10, v11);
                *(unsigned*)&g_hh[(size_t)(side * NN + row1) * HD + col] = *(unsigned*)&h;
            }
        } else {
            if (row0 < NN) red2(&g_z.pool[side][batch[row0] * HD + col], v00, v01);
            if (row1 < NN) red2(&g_z.pool[side][batch[row1] * HD + col], v10, v11);
        }
    }
}

// ---------------- final MLP ---------------------------------------------------
__global__ void k_final(const float* __restrict__ lW0, const float* __restrict__ lb0,
                        const float* __restrict__ lW1, const float* __restrict__ lb1,
                        float* __restrict__ out) {
    int g = blockIdx.x;
    int j = threadIdx.x;                                 // 96 threads
    __shared__ float cat[2 * HD + 2 * FIN];              // 320
    __shared__ float red[HD];
    for (int i = j; i < 2 * HD + 2 * FIN; i += HD) {
        float v;
        if (i < HD)            v = g_z.pool[0][g * HD + i] / fmaxf((float)g_z.cnt[0][g], 1.f);
        else if (i < 2 * HD)   v = g_z.pool[1][g * HD + (i - HD)] / fmaxf((float)g_z.cnt[1][g], 1.f);
        else if (i < 2 * HD + FIN) v = g_z.att[0][g * FIN + (i - 2 * HD)];
        else                   v = g_z.att[1][g * FIN + (i - 2 * HD - FIN)];
        cat[i] = v;
    }
    __syncthreads();
    float acc = lb0[j];
#pragma unroll 8
    for (int i = 0; i < 2 * HD + 2 * FIN; i++)
        acc += cat[i] * lW0[i * HD + j];
    red[j] = fmaxf(acc, 0.f) * lW1[j];
    __syncthreads();
    if (j == 0) {
        float s = lb1[0];
        for (int t = 0; t < HD; t++) s += red[t];
        out[g] = s;
    }
}

// ---------------- host launcher ----------------------------------------------
extern "C" void kernel_launch(void* const* d_in, const int* in_sizes, int n_in,
                              void* d_out, int out_size) {
    const float* xp  = (const float*)d_in[0];
    const float* xd  = (const float*)d_in[1];
    const int*   eip = (const int*)d_in[4];
    const int*   eid = (const int*)d_in[5];
    const int*   bp  = (const int*)d_in[6];
    const int*   bd  = (const int*)d_in[7];
    const float* Wp0 = (const float*)d_in[8],  *bp0 = (const float*)d_in[9];
    const float* Wp1 = (const float*)d_in[10], *bp1 = (const float*)d_in[11];
    const float* Wp2 = (const float*)d_in[12], *bp2 = (const float*)d_in[13];
    const float* Wd0 = (const float*)d_in[14], *bd0 = (const float*)d_in[15];
    const float* Wd1 = (const float*)d_in[16], *bd1 = (const float*)d_in[17];
    const float* Wd2 = (const float*)d_in[18], *bd2 = (const float*)d_in[19];
    const float* gW1 = (const float*)d_in[20], *gb1 = (const float*)d_in[21];
    const float* gW2 = (const float*)d_in[22], *gb2 = (const float*)d_in[23];
    const float* lW0 = (const float*)d_in[24], *lb0 = (const float*)d_in[25];
    const float* lW1 = (const float*)d_in[26], *lb1 = (const float*)d_in[27];

    const int TB = 256;
    const int GB_E2 = (NE2 + TB - 1) / TB;
    const int GB_C16 = (NN2 * 16 + TB - 1) / TB;
    const int GB_H8  = (NN2 * 8 + TB - 1) / TB;
    const int GB_H12 = (NN2 * 12 + TB - 1) / TB;
    const int GEMM_GRID = 782;                       // 391 tiles x 2 sides
    const int SMEM96 = (128 + 96 + 96) * (96 + 8) * 2;   // 66560 B
    const int SMEM64 = (128 + 96 + 96) * (64 + 8) * 2;   // 46080 B

    static cudaStream_t s2 = nullptr;
    static cudaEvent_t ev1 = nullptr, ev2 = nullptr;
    static int inited = 0;
    if (!inited) {
        cudaFuncSetAttribute(k_gemm_mma, cudaFuncAttributeMaxDynamicSharedMemorySize, SMEM96);
        cudaStreamCreateWithFlags(&s2, cudaStreamNonBlocking);
        cudaEventCreateWithFlags(&ev1, cudaEventDisableTiming);
        cudaEventCreateWithFlags(&ev2, cudaEventDisableTiming);
        inited = 1;
    }

    void* xh_dev = nullptr;  cudaGetSymbolAddress(&xh_dev, g_xh);
    void* hh_dev = nullptr;  cudaGetSymbolAddress(&hh_dev, g_hh);
    void* deg_dev = nullptr; cudaGetSymbolAddress(&deg_dev, g_deg);
    void* z_dev = nullptr;   cudaGetSymbolAddress(&z_dev, g_z);

    // ---- fork: stream B handles zero-init + tohalf + gate + attpool ----
    cudaEventRecord(ev1, 0);
    cudaStreamWaitEvent(s2, ev1, 0);

    // stream B
    cudaMemsetAsync(z_dev, 0, sizeof(ZeroBlk), s2);
    k_tohalf<<<GB_C16, TB, 0, s2>>>((const float4*)xp, (const float4*)xd);
    k_gate<<<(NN2 + 7) / 8, 256, 0, s2>>>(xp, xd, bp, bd, gW1, gb1, gW2, gb2);
    k_attpool<<<GB_C16, TB, 0, s2>>>(xp, xd, bp, bd);
    cudaEventRecord(ev2, s2);

    // stream A (default): CSR build
    cudaMemsetAsync(deg_dev, 0, NN2 * sizeof(int), 0);
    k_deg<<<GB_E2, TB>>>(eip, eid);
    k_scan1<<<NSCB2, SCB>>>();
    k_scan3<<<NSCB2, SCB>>>();
    k_csrfill<<<GB_E2, TB>>>(eip, eid);

    // ---- join: gathers need tohalf (B) + csrfill (A); gemm2 needs pool zeroed (B)
    cudaStreamWaitEvent(0, ev2, 0);

    // layer 0: gather x (K=64) -> aggh; HMMA GEMM 64->96 (+relu) -> g_hh
    k_gatherh<<<GB_H8, TB>>>((const int4*)xh_dev, 8);
    k_gemm_mma<<<GEMM_GRID, 256, SMEM64>>>(Wp0, Wd0, bp0, bd0, 64, 1, 0, bp, bd);
    // layer 1
    k_gatherh<<<GB_H12, TB>>>((const int4*)hh_dev, 12);
    k_gemm_mma<<<GEMM_GRID, 256, SMEM96>>>(Wp1, Wd1, bp1, bd1, 96, 1, 0, bp, bd);
    // layer 2 (+ fused mean-pool sums)
    k_gatherh<<<GB_H12, TB>>>((const int4*)hh_dev, 12);
    k_gemm_mma<<<GEMM_GRID, 256, SMEM96>>>(Wp2, Wd2, bp2, bd2, 96, 0, 1, bp, bd);

    k_final<<<NG, HD>>>(lW0, lb0, lW1, lb1, (float*)d_out);
}

// round 10
// speedup vs baseline: 1.9589x; 1.0079x over previous
#include <cuda_runtime.h>
#include <cuda_fp16.h>
#include <math.h>

#define NN 50000
#define NN2 100000
#define NE 800000
#define NE2 1600000
#define FIN 64
#define HD 96
#define NG 256
#define SCB 512
#define NSCB2 ((NN2 + SCB - 1) / SCB)   // 196

// ---------------- scratch (device globals; no runtime allocation) -----------
__device__ __align__(16) __half g_hh[NN2 * HD];   // layer outputs, fp16
__device__ __align__(16) __half g_xh[NN2 * FIN];  // input features, fp16
__device__ __align__(16) __half g_aggh[NN2 * HD]; // gather outputs, fp16
__device__ float g_dinv[NN2];
__device__ int   g_deg[NN2];
__device__ int   g_coff[NN2 + 1];
__device__ int   g_cur[NN2];
__device__ __align__(8) int2 g_edge[NE2];         // (local src, norm-bits)
__device__ int   g_bsum[256];
__device__ float g_gate[NN2];

// zero-initialized-per-iteration block (single memset)
struct __align__(16) ZeroBlk {
    float gden[2][NG];
    int   cnt[2][NG];
    float att[2][NG * FIN];
    float pool[2][NG * HD];
};
__device__ ZeroBlk g_z;

// ---------------- helpers ----------------------------------------------------
__device__ __forceinline__ void red4(float* p, float4 v) {
    asm volatile("red.global.add.v4.f32 [%0], {%1,%2,%3,%4};"
                 :: "l"(p), "f"(v.x), "f"(v.y), "f"(v.z), "f"(v.w) : "memory");
}
__device__ __forceinline__ void red2(float* p, float a, float b) {
    asm volatile("red.global.add.v2.f32 [%0], {%1,%2};"
                 :: "l"(p), "f"(a), "f"(b) : "memory");
}

__device__ __forceinline__ void mma16816(float* c, const unsigned* a, unsigned b0, unsigned b1) {
    asm volatile(
        "mma.sync.aligned.m16n8k16.row.col.f32.f16.f16.f32 "
        "{%0,%1,%2,%3}, {%4,%5,%6,%7}, {%8,%9}, {%0,%1,%2,%3};"
        : "+f"(c[0]), "+f"(c[1]), "+f"(c[2]), "+f"(c[3])
        : "r"(a[0]), "r"(a[1]), "r"(a[2]), "r"(a[3]), "r"(b0), "r"(b1));
}

// acc[0..7] += w * (8 halves in raw)
__device__ __forceinline__ void fma8(int4 raw, float w, float* acc) {
    __half2* h = reinterpret_cast<__half2*>(&raw);
#pragma unroll
    for (int i = 0; i < 4; i++) {
        float2 f = __half22float2(h[i]);
        acc[2 * i]     += w * f.x;
        acc[2 * i + 1] += w * f.y;
    }
}

// ---------------- input conversion ---------------------------------------------
__global__ void k_tohalf(const float4* __restrict__ xp, const float4* __restrict__ xd) {
    int idx = blockIdx.x * blockDim.x + threadIdx.x;      // NN2 * 16
    if (idx >= NN2 * 16) return;
    int n = idx >> 4;
    int side = (n >= NN);
    int nl = n - side * NN;
    float4 v = __ldg(&(side ? xd : xp)[nl * 16 + (idx & 15)]);
    __half2 h0 = __floats2half2_rn(v.x, v.y);
    __half2 h1 = __floats2half2_rn(v.z, v.w);
    uint2 u;
    u.x = *(unsigned*)&h0; u.y = *(unsigned*)&h1;
    ((uint2*)g_xh)[idx] = u;
}

__global__ void k_deg(const int* __restrict__ eip, const int* __restrict__ eid) {
    int e = blockIdx.x * blockDim.x + threadIdx.x;
    if (e >= NE2) return;
    int side = (e >= NE);
    int el = e - side * NE;
    const int* ei = side ? eid : eip;
    atomicAdd(&g_deg[side * NN + ei[NE + el]], 1);
}

// ---------------- CSR build ----------------------------------------------------
__global__ void k_scan1() {
    __shared__ int s[SCB];
    int i = blockIdx.x * SCB + threadIdx.x;
    s[threadIdx.x] = (i < NN2) ? g_deg[i] : 0;
    __syncthreads();
    for (int o = SCB / 2; o > 0; o >>= 1) {
        if (threadIdx.x < o) s[threadIdx.x] += s[threadIdx.x + o];
        __syncthreads();
    }
    if (threadIdx.x == 0) g_bsum[blockIdx.x] = s[0];
}

// scan3: per-block offset computed in-block from g_bsum
__global__ void k_scan3() {
    __shared__ int sb[SCB];
    int t = threadIdx.x;
    sb[t] = (t < blockIdx.x) ? g_bsum[t] : 0;       // blockIdx.x < 196 <= SCB
    __syncthreads();
    for (int o = SCB / 2; o > 0; o >>= 1) {
        if (t < o) sb[t] += sb[t + o];
        __syncthreads();
    }
    int boff = sb[0];
    __syncthreads();
    int i = blockIdx.x * SCB + t;
    int v = (i < NN2) ? g_deg[i] : 0;
    sb[t] = v;
    __syncthreads();
    for (int o = 1; o < SCB; o <<= 1) {
        int a = (t >= o) ? sb[t - o] : 0;
        __syncthreads();
        sb[t] += a;
        __syncthreads();
    }
    if (i < NN2) {
        int off = boff + sb[t] - v;                 // exclusive
        g_coff[i] = off;
        g_cur[i] = off;
        g_dinv[i] = rsqrtf((float)v + 1.0f);
    }
    if (blockIdx.x == NSCB2 - 1 && t == SCB - 1) g_coff[NN2] = boff + sb[t];
}

__global__ void k_csrfill(const int* __restrict__ eip, const int* __restrict__ eid) {
    int e = blockIdx.x * blockDim.x + threadIdx.x;
    if (e >= NE2) return;
    int side = (e >= NE);
    int el = e - side * NE;
    const int* ei = side ? eid : eip;
    int s = ei[el], d = ei[NE + el];
    int base = side * NN;
    float norm = g_dinv[base + s] * g_dinv[base + d];
    int slot = atomicAdd(&g_cur[base + d], 1);
    g_edge[slot] = make_int2(s, __float_as_int(norm));
}

// ---------------- attention gate (both sides) ----------------------------------
__global__ void k_gate(const float* __restrict__ xp, const float* __restrict__ xd,
                       const int* __restrict__ bp, const int* __restrict__ bd,
                       const float* __restrict__ gW1, const float* __restrict__ gb1,
                       const float* __restrict__ gW2, const float* __restrict__ gb2) {
    int lane = threadIdx.x & 31;
    int n = blockIdx.x * (blockDim.x >> 5) + (threadIdx.x >> 5);
    if (n >= NN2) return;
    int side = (n >= NN);
    int nl = n - side * NN;
    const float* x = side ? xd : xp;
    const int* batch = side ? bd : bp;
    float xa = x[nl * FIN + lane];
    float xb = x[nl * FIN + 32 + lane];
    float acc0 = gb1[lane];
    float acc1 = gb1[lane + 32];
#pragma unroll
    for (int k = 0; k < FIN; k++) {
        float xk = __shfl_sync(0xffffffffu, (k < 32) ? xa : xb, k & 31);
        acc0 += xk * gW1[k * FIN + lane];
        acc1 += xk * gW1[k * FIN + lane + 32];
    }
    float h = fmaxf(acc0, 0.f) * gW2[lane] + fmaxf(acc1, 0.f) * gW2[lane + 32];
#pragma unroll
    for (int o = 16; o > 0; o >>= 1) h += __shfl_down_sync(0xffffffffu, h, o);
    if (lane == 0) {
        float e = expf(h + gb2[0]);        // gates tiny: no max-shift needed
        g_gate[n] = e;
        int b = batch[nl];
        atomicAdd(&g_z.gden[side][b], e);
        atomicAdd(&g_z.cnt[side][b], 1);
    }
}

__global__ void k_attpool(const float* __restrict__ xp, const float* __restrict__ xd,
                          const int* __restrict__ bp, const int* __restrict__ bd) {
    int idx = blockIdx.x * blockDim.x + threadIdx.x;     // NN2 * 16
    if (idx >= NN2 * (FIN / 4)) return;
    int n = idx >> 4, j = idx & 15;
    int side = (n >= NN);
    int nl = n - side * NN;
    int b = side ? bd[nl] : bp[nl];
    float alpha = g_gate[n] / g_z.gden[side][b];
    const float4* x4 = side ? (const float4*)xd : (const float4*)xp;
    float4 v = __ldg(&x4[nl * (FIN / 4) + j]);
    v.x *= alpha; v.y *= alpha; v.z *= alpha; v.w *= alpha;
    red4(&g_z.att[side][b * FIN + j * 4], v);
}

// ---------------- fp16 CSR gather -> fp16 agg (4-wide edge unroll) -------------
__global__ void k_gatherh(const int4* __restrict__ f16, int K8) {
    int idx = blockIdx.x * blockDim.x + threadIdx.x;
    if (idx >= NN2 * K8) return;
    int n = idx / K8, j = idx - n * K8;
    int base = (n >= NN) ? NN : 0;
    float dv = g_dinv[n];
    float acc[8] = {0.f, 0.f, 0.f, 0.f, 0.f, 0.f, 0.f, 0.f};
    fma8(__ldg(&f16[(size_t)n * K8 + j]), dv * dv, acc);
    int p = __ldg(&g_coff[n]);
    int end = __ldg(&g_coff[n + 1]);
    for (; p + 3 < end; p += 4) {
        int2 e0 = __ldg(&g_edge[p]);
        int2 e1 = __ldg(&g_edge[p + 1]);
        int2 e2 = __ldg(&g_edge[p + 2]);
        int2 e3 = __ldg(&g_edge[p + 3]);
        int4 a0 = __ldg(&f16[(size_t)(base + e0.x) * K8 + j]);
        int4 a1 = __ldg(&f16[(size_t)(base + e1.x) * K8 + j]);
        int4 a2 = __ldg(&f16[(size_t)(base + e2.x) * K8 + j]);
        int4 a3 = __ldg(&f16[(size_t)(base + e3.x) * K8 + j]);
        fma8(a0, __int_as_float(e0.y), acc);
        fma8(a1, __int_as_float(e1.y), acc);
        fma8(a2, __int_as_float(e2.y), acc);
        fma8(a3, __int_as_float(e3.y), acc);
    }
    for (; p < end; p++) {
        int2 e0 = __ldg(&g_edge[p]);
        fma8(__ldg(&f16[(size_t)(base + e0.x) * K8 + j]), __int_as_float(e0.y), acc);
    }
    __half2 h0 = __floats2half2_rn(acc[0], acc[1]);
    __half2 h1 = __floats2half2_rn(acc[2], acc[3]);
    __half2 h2 = __floats2half2_rn(acc[4], acc[5]);
    __half2 h3 = __floats2half2_rn(acc[6], acc[7]);
    int4 o;
    o.x = *(int*)&h0; o.y = *(int*)&h1; o.z = *(int*)&h2; o.w = *(int*)&h3;
    ((int4*)g_aggh)[idx] = o;
}

// ---------------- HMMA GEMM: out[rows,96] = aggh[rows,K] @ W[K,96] + b ----------
__global__ void __launch_bounds__(256) k_gemm_mma(
        const float* __restrict__ Wp, const float* __restrict__ Wd,
        const float* __restrict__ bp, const float* __restrict__ bd,
        int K, int reluOut, int fusePool,
        const int* __restrict__ batch_p, const int* __restrict__ batch_d) {
    extern __shared__ __half sm[];
    const int KS = K + 8;
    __half* As  = sm;                     // 128 x KS
    __half* Bhi = As + 128 * KS;          // 96 x KS  ([n][k])
    __half* Blo = Bhi + 96 * KS;
    const int side = blockIdx.x & 1;
    const int tile = blockIdx.x >> 1;
    const int rowBase = tile * 128;
    const float* W = side ? Wd : Wp;
    const float* bias = side ? bd : bp;
    const int* batch = side ? batch_d : batch_p;
    const int tid = threadIdx.x;
    const int K8 = K >> 3;

    for (int i = tid; i < K * HD; i += 256) {
        int k = i / HD, n = i - k * HD;
        float w = __ldg(&W[i]);
        __half hi = __float2half_rn(w);
        __half lo = __float2half_rn(w - __half2float(hi));
        Bhi[n * KS + k] = hi;
        Blo[n * KS + k] = lo;
    }
    const int4* Ah = (const int4*)g_aggh;
    for (int i = tid; i < 128 * K8; i += 256) {
        int r = i / K8, j = i - r * K8;
        int row = rowBase + r;
        int4 v = make_int4(0, 0, 0, 0);
        if (row < NN) v = __ldg(&Ah[(size_t)(side * NN + row) * K8 + j]);
        *(int4*)&As[r * KS + j * 8] = v;
    }
    __syncthreads();

    const int warp = tid >> 5;
    const int lane = tid & 31;
    const int g = lane >> 2;
    const int tg = lane & 3;
    const int warpRow = warp * 16;

    float c[12][4];
#pragma unroll
    for (int nt = 0; nt < 12; nt++)
#pragma unroll
        for (int q = 0; q < 4; q++) c[nt][q] = 0.f;

    const int nk = K >> 4;
    for (int ks = 0; ks < nk; ks++) {
        unsigned a[4];
        const __half* arow0 = &As[(warpRow + g) * KS + ks * 16 + tg * 2];
        const __half* arow1 = arow0 + 8 * KS;
        a[0] = *(const unsigned*)arow0;
        a[1] = *(const unsigned*)arow1;
        a[2] = *(const unsigned*)(arow0 + 8);
        a[3] = *(const unsigned*)(arow1 + 8);
#pragma unroll
        for (int nt = 0; nt < 12; nt++) {
            const __half* brow = &Bhi[(nt * 8 + g) * KS + ks * 16 + tg * 2];
            unsigned b0 = *(const unsigned*)brow;
            unsigned b1 = *(const unsigned*)(brow + 8);
            mma16816(c[nt], a, b0, b1);
            const __half* brl = &Blo[(nt * 8 + g) * KS + ks * 16 + tg * 2];
            unsigned l0 = *(const unsigned*)brl;
            unsigned l1 = *(const unsigned*)(brl + 8);
            mma16816(c[nt], a, l0, l1);
        }
    }

    int row0 = rowBase + warpRow + g;
    int row1 = row0 + 8;
#pragma unroll
    for (int nt = 0; nt < 12; nt++) {
        int col = nt * 8 + tg * 2;
        float bx = __ldg(&bias[col]);
        float by = __ldg(&bias[col + 1]);
        float v00 = c[nt][0] + bx, v01 = c[nt][1] + by;
        float v10 = c[nt][2] + bx, v11 = c[nt][3] + by;
        if (!fusePool) {
            if (reluOut) {
                v00 = fmaxf(v00, 0.f); v01 = fmaxf(v01, 0.f);
                v10 = fmaxf(v10, 0.f); v11 = fmaxf(v11, 0.f);
            }
            if (row0 < NN) {
                __half2 h = __floats2half2_rn(v00, v01);
                *(unsigned*)&g_hh[(size_t)(side * NN + row0) * HD + col] = *(unsigned*)&h;
            }
            if (row1 < NN) {
                __half2 h = __floats2half2_rn(v10, v11);
                *(unsigned*)&g_hh[(size_t)(side * NN + row1) * HD + col] = *(unsigned*)&h;
            }
        } else {
            if (row0 < NN) red2(&g_z.pool[side][batch[row0] * HD + col], v00, v01);
            if (row1 < NN) red2(&g_z.pool[side][batch[row1] * HD + col], v10, v11);
        }
    }
}

// ---------------- final MLP ---------------------------------------------------
__global__ void k_final(const float* __restrict__ lW0, const float* __restrict__ lb0,
                        const float* __restrict__ lW1, const float* __restrict__ lb1,
                        float* __restrict__ out) {
    int g = blockIdx.x;
    int j = threadIdx.x;                                 // 96 threads
    __shared__ float cat[2 * HD + 2 * FIN];              // 320
    __shared__ float red[HD];
    for (int i = j; i < 2 * HD + 2 * FIN; i += HD) {
        float v;
        if (i < HD)            v = g_z.pool[0][g * HD + i] / fmaxf((float)g_z.cnt[0][g], 1.f);
        else if (i < 2 * HD)   v = g_z.pool[1][g * HD + (i - HD)] / fmaxf((float)g_z.cnt[1][g], 1.f);
        else if (i < 2 * HD + FIN) v = g_z.att[0][g * FIN + (i - 2 * HD)];
        else                   v = g_z.att[1][g * FIN + (i - 2 * HD - FIN)];
        cat[i] = v;
    }
    __syncthreads();
    float acc = lb0[j];
#pragma unroll 8
    for (int i = 0; i < 2 * HD + 2 * FIN; i++)
        acc += cat[i] * lW0[i * HD + j];
    red[j] = fmaxf(acc, 0.f) * lW1[j];
    __syncthreads();
    if (j == 0) {
        float s = lb1[0];
        for (int t = 0; t < HD; t++) s += red[t];
        out[g] = s;
    }
}

// ---------------- host launcher ----------------------------------------------
extern "C" void kernel_launch(void* const* d_in, const int* in_sizes, int n_in,
                              void* d_out, int out_size) {
    const float* xp  = (const float*)d_in[0];
    const float* xd  = (const float*)d_in[1];
    const int*   eip = (const int*)d_in[4];
    const int*   eid = (const int*)d_in[5];
    const int*   bp  = (const int*)d_in[6];
    const int*   bd  = (const int*)d_in[7];
    const float* Wp0 = (const float*)d_in[8],  *bp0 = (const float*)d_in[9];
    const float* Wp1 = (const float*)d_in[10], *bp1 = (const float*)d_in[11];
    const float* Wp2 = (const float*)d_in[12], *bp2 = (const float*)d_in[13];
    const float* Wd0 = (const float*)d_in[14], *bd0 = (const float*)d_in[15];
    const float* Wd1 = (const float*)d_in[16], *bd1 = (const float*)d_in[17];
    const float* Wd2 = (const float*)d_in[18], *bd2 = (const float*)d_in[19];
    const float* gW1 = (const float*)d_in[20], *gb1 = (const float*)d_in[21];
    const float* gW2 = (const float*)d_in[22], *gb2 = (const float*)d_in[23];
    const float* lW0 = (const float*)d_in[24], *lb0 = (const float*)d_in[25];
    const float* lW1 = (const float*)d_in[26], *lb1 = (const float*)d_in[27];

    const int TB = 256;
    const int GB_E2 = (NE2 + TB - 1) / TB;
    const int GB_C16 = (NN2 * 16 + TB - 1) / TB;
    const int GB_H8  = (NN2 * 8 + TB - 1) / TB;
    const int GB_H12 = (NN2 * 12 + TB - 1) / TB;
    const int GEMM_GRID = 782;                       // 391 tiles x 2 sides
    const int SMEM96 = (128 + 96 + 96) * (96 + 8) * 2;   // 66560 B
    const int SMEM64 = (128 + 96 + 96) * (64 + 8) * 2;   // 46080 B

    static cudaStream_t s2 = nullptr;
    static cudaEvent_t ev1 = nullptr, evT = nullptr, ev2 = nullptr;
    static int inited = 0;
    if (!inited) {
        cudaFuncSetAttribute(k_gemm_mma, cudaFuncAttributeMaxDynamicSharedMemorySize, SMEM96);
        cudaStreamCreateWithFlags(&s2, cudaStreamNonBlocking);
        cudaEventCreateWithFlags(&ev1, cudaEventDisableTiming);
        cudaEventCreateWithFlags(&evT, cudaEventDisableTiming);
        cudaEventCreateWithFlags(&ev2, cudaEventDisableTiming);
        inited = 1;
    }

    void* xh_dev = nullptr;  cudaGetSymbolAddress(&xh_dev, g_xh);
    void* hh_dev = nullptr;  cudaGetSymbolAddress(&hh_dev, g_hh);
    void* deg_dev = nullptr; cudaGetSymbolAddress(&deg_dev, g_deg);
    void* z_dev = nullptr;   cudaGetSymbolAddress(&z_dev, g_z);

    // ---- fork ----
    cudaEventRecord(ev1, 0);
    cudaStreamWaitEvent(s2, ev1, 0);

    // stream B: zero-init, tohalf (needed by gathers), then gate+attpool
    cudaMemsetAsync(z_dev, 0, sizeof(ZeroBlk), s2);
    k_tohalf<<<GB_C16, TB, 0, s2>>>((const float4*)xp, (const float4*)xd);
    cudaEventRecord(evT, s2);                 // gathers need only this from B
    k_gate<<<(NN2 + 7) / 8, 256, 0, s2>>>(xp, xd, bp, bd, gW1, gb1, gW2, gb2);
    k_attpool<<<GB_C16, TB, 0, s2>>>(xp, xd, bp, bd);
    cudaEventRecord(ev2, s2);                 // k_final needs this

    // stream A (default): CSR build
    cudaMemsetAsync(deg_dev, 0, NN2 * sizeof(int), 0);
    k_deg<<<GB_E2, TB>>>(eip, eid);
    k_scan1<<<NSCB2, SCB>>>();
    k_scan3<<<NSCB2, SCB>>>();
    k_csrfill<<<GB_E2, TB>>>(eip, eid);

    // join #1: gathers need tohalf; attpool continues concurrently on B
    cudaStreamWaitEvent(0, evT, 0);

    // layer 0: gather x (K=64) -> aggh; HMMA GEMM 64->96 (+relu) -> g_hh
    k_gatherh<<<GB_H8, TB>>>((const int4*)xh_dev, 8);
    k_gemm_mma<<<GEMM_GRID, 256, SMEM64>>>(Wp0, Wd0, bp0, bd0, 64, 1, 0, bp, bd);
    // layer 1
    k_gatherh<<<GB_H12, TB>>>((const int4*)hh_dev, 12);
    k_gemm_mma<<<GEMM_GRID, 256, SMEM96>>>(Wp1, Wd1, bp1, bd1, 96, 1, 0, bp, bd);
    // layer 2 (+ fused mean-pool sums)
    k_gatherh<<<GB_H12, TB>>>((const int4*)hh_dev, 12);
    k_gemm_mma<<<GEMM_GRID, 256, SMEM96>>>(Wp2, Wd2, bp2, bd2, 96, 0, 1, bp, bd);

    // join #2: k_final reads g_z.att / g_z.gden written on stream B
    cudaStreamWaitEvent(0, ev2, 0);
    k_final<<<NG, HD>>>(lW0, lb0, lW1, lb1, (float*)d_out);
}